// round 4
// baseline (speedup 1.0000x reference)
#include <cuda_runtime.h>
#include <cuda_bf16.h>
#include <math.h>

// Problem constants (from reference): T=1024 tokens, H=2048 hidden,
// I=4096 intermediate, E=8 experts.
#define T_TOK 1024
#define H_DIM 2048
#define I_DIM 4096
#define E_EXP 8
#define TWO_I (2 * I_DIM)
#define JITTER2 0.02f   // 2 * JITTER_EPS

// ---------------------------------------------------------------------------
// Device-global scratch (allocation-free rule: __device__ globals only)
// ---------------------------------------------------------------------------
__device__ int   g_cnt[E_EXP];                                    // tokens per expert
__device__ int   g_tok [E_EXP * T_TOK];                           // gathered token ids
__device__ float g_mult[E_EXP * T_TOK];                           // gate multiplier per slot
__device__ float g_gu [(size_t)E_EXP * T_TOK * TWO_I];            // 256 MB: gate_up
__device__ float g_act[(size_t)E_EXP * T_TOK * I_DIM];            // 128 MB: silu(g)*u

// ---------------------------------------------------------------------------
// Kernel 0: zero output + expert counters (must re-run every graph replay)
// ---------------------------------------------------------------------------
__global__ void k_init(float* __restrict__ out) {
    int i = blockIdx.x * blockDim.x + threadIdx.x;
    if (i < E_EXP) g_cnt[i] = 0;
    if (i < T_TOK * H_DIM) out[i] = 0.0f;
}

// ---------------------------------------------------------------------------
// Kernel 1: router logits + sparsemixer + build per-expert token lists.
// One block per token; warp w computes dot(x[t], gate_w[w]).
// ---------------------------------------------------------------------------
__global__ void k_router(const float* __restrict__ x, const float* __restrict__ gw) {
    int t    = blockIdx.x;
    int warp = threadIdx.x >> 5;
    int lane = threadIdx.x & 31;

    const float4* xr = (const float4*)(x + (size_t)t * H_DIM);
    const float4* gr = (const float4*)(gw + (size_t)warp * H_DIM);

    float s = 0.0f;
    for (int i = lane; i < H_DIM / 4; i += 32) {
        float4 a = xr[i];
        float4 b = gr[i];
        s += a.x * b.x + a.y * b.y + a.z * b.z + a.w * b.w;
    }
#pragma unroll
    for (int o = 16; o > 0; o >>= 1) s += __shfl_xor_sync(0xFFFFFFFFu, s, o);

    __shared__ float sc[E_EXP];
    if (lane == 0) sc[warp] = s;
    __syncthreads();

    if (threadIdx.x == 0) {
        float sco[E_EXP];
#pragma unroll
        for (int e = 0; e < E_EXP; ++e) sco[e] = sc[e];

        // --- first expert ---
        float max1 = sco[0]; int ind1 = 0;
#pragma unroll
        for (int e = 1; e < E_EXP; ++e)
            if (sco[e] > max1) { max1 = sco[e]; ind1 = e; }
        float sum1 = 0.0f;
#pragma unroll
        for (int e = 0; e < E_EXP; ++e) {
            float factor = fmaxf(fabsf(sco[e]), max1);
            bool masked = (max1 - sco[e]) / factor > JITTER2;
            if (!masked) sum1 += expf(sco[e] - max1);
        }
        float mult1 = 1.0f / sum1;   // exp(max1-max1)/sum1

        // --- second expert (exclude ind1) ---
        float max2 = -INFINITY; int ind2 = 0;
#pragma unroll
        for (int e = 0; e < E_EXP; ++e)
            if (e != ind1 && sco[e] > max2) { max2 = sco[e]; ind2 = e; }
        float sum2 = 0.0f;
#pragma unroll
        for (int e = 0; e < E_EXP; ++e) {
            if (e == ind1) continue;                  // masked_scores[ind1] = -inf
            float factor = fmaxf(fabsf(sco[e]), max2);
            bool masked = (max2 - sco[e]) / factor > JITTER2;
            if (!masked) sum2 += expf(sco[e] - max2);
        }
        float mult2 = 1.0f / sum2;

        int p1 = atomicAdd(&g_cnt[ind1], 1);
        g_tok [ind1 * T_TOK + p1] = t;
        g_mult[ind1 * T_TOK + p1] = mult1;
        int p2 = atomicAdd(&g_cnt[ind2], 1);
        g_tok [ind2 * T_TOK + p2] = t;
        g_mult[ind2 * T_TOK + p2] = mult2;
    }
}

// ---------------------------------------------------------------------------
// Grouped SGEMM 1: gu[e, m, n] = sum_h x[tok[e,m], h] * ws[e, n, h]
// 128x128 tile, BK=8, 8x8 microtile, 256 threads.
// blockIdx.x = m-tile (fast: consecutive blocks share the B tile -> L2 reuse)
// blockIdx.y = n-tile (TWO_I/128 = 64), blockIdx.z = expert.
// ---------------------------------------------------------------------------
__global__ __launch_bounds__(256, 2)
void k_ffn1(const float* __restrict__ x, const float* __restrict__ ws) {
    int e  = blockIdx.z;
    int Me = g_cnt[e];
    int m0 = blockIdx.x * 128;
    if (m0 >= Me) return;
    int n0 = blockIdx.y * 128;

    const float* B = ws + (size_t)e * TWO_I * H_DIM + (size_t)n0 * H_DIM;

    __shared__ __align__(16) float As[8][132];
    __shared__ __align__(16) float Bs[8][132];
    __shared__ int stok[128];

    int tid = threadIdx.x;
    if (tid < 128) {
        int m = m0 + tid;
        stok[tid] = (m < Me) ? g_tok[e * T_TOK + m] : g_tok[e * T_TOK];
    }
    __syncthreads();

    int lr = tid >> 1;          // tile row 0..127 for loading
    int lk = (tid & 1) * 4;     // k sub-offset 0 or 4
    int tx = tid & 15;          // 16x16 thread grid for compute
    int ty = tid >> 4;
    const float* Arow = x + (size_t)stok[lr] * H_DIM + lk;
    const float* Brow = B + (size_t)lr * H_DIM + lk;

    float acc[8][8];
#pragma unroll
    for (int i = 0; i < 8; ++i)
#pragma unroll
        for (int j = 0; j < 8; ++j) acc[i][j] = 0.0f;

    for (int k0 = 0; k0 < H_DIM; k0 += 8) {
        float4 a = *(const float4*)(Arow + k0);
        float4 b = *(const float4*)(Brow + k0);
        As[lk + 0][lr] = a.x; As[lk + 1][lr] = a.y;
        As[lk + 2][lr] = a.z; As[lk + 3][lr] = a.w;
        Bs[lk + 0][lr] = b.x; Bs[lk + 1][lr] = b.y;
        Bs[lk + 2][lr] = b.z; Bs[lk + 3][lr] = b.w;
        __syncthreads();
#pragma unroll
        for (int kk = 0; kk < 8; ++kk) {
            float ra[8], rb[8];
            *(float4*)(&ra[0]) = *(const float4*)(&As[kk][ty * 8]);
            *(float4*)(&ra[4]) = *(const float4*)(&As[kk][ty * 8 + 4]);
            *(float4*)(&rb[0]) = *(const float4*)(&Bs[kk][tx * 8]);
            *(float4*)(&rb[4]) = *(const float4*)(&Bs[kk][tx * 8 + 4]);
#pragma unroll
            for (int i = 0; i < 8; ++i)
#pragma unroll
                for (int j = 0; j < 8; ++j)
                    acc[i][j] += ra[i] * rb[j];
        }
        __syncthreads();
    }

    // Store to gu scratch (only valid rows)
#pragma unroll
    for (int i = 0; i < 8; ++i) {
        int m = m0 + ty * 8 + i;
        if (m < Me) {
            float* dst = g_gu + ((size_t)e * T_TOK + m) * TWO_I + n0 + tx * 8;
            *(float4*)(dst)     = *(float4*)(&acc[i][0]);
            *(float4*)(dst + 4) = *(float4*)(&acc[i][4]);
        }
    }
}

// ---------------------------------------------------------------------------
// SiLU gating: act = silu(g) * u
// ---------------------------------------------------------------------------
__global__ void k_silu() {
    int e = blockIdx.z;
    int m = blockIdx.y;
    if (m >= g_cnt[e]) return;
    int i = (blockIdx.x * blockDim.x + threadIdx.x) * 4;
    const float* gu = g_gu + ((size_t)e * T_TOK + m) * TWO_I;
    float4 g = *(const float4*)(gu + i);
    float4 u = *(const float4*)(gu + I_DIM + i);
    float4 r;
    r.x = g.x / (1.0f + expf(-g.x)) * u.x;
    r.y = g.y / (1.0f + expf(-g.y)) * u.y;
    r.z = g.z / (1.0f + expf(-g.z)) * u.z;
    r.w = g.w / (1.0f + expf(-g.w)) * u.w;
    *(float4*)(g_act + ((size_t)e * T_TOK + m) * I_DIM + i) = r;
}

// ---------------------------------------------------------------------------
// Grouped SGEMM 2 + scatter: out[tok, n] += mult * sum_i act[e,m,i]*w2s[e,n,i]
// Same tiling as ffn1; K = I_DIM = 4096, N = H_DIM = 2048.
// ---------------------------------------------------------------------------
__global__ __launch_bounds__(256, 2)
void k_ffn2(const float* __restrict__ w2s, float* __restrict__ out) {
    int e  = blockIdx.z;
    int Me = g_cnt[e];
    int m0 = blockIdx.x * 128;
    if (m0 >= Me) return;
    int n0 = blockIdx.y * 128;

    const float* A = g_act + ((size_t)e * T_TOK + m0) * I_DIM;
    const float* B = w2s + (size_t)e * H_DIM * I_DIM + (size_t)n0 * I_DIM;

    __shared__ __align__(16) float As[8][132];
    __shared__ __align__(16) float Bs[8][132];
    __shared__ int   stok[128];
    __shared__ float smul[128];

    int tid = threadIdx.x;
    if (tid < 128) {
        int m = m0 + tid;
        stok[tid] = (m < Me) ? g_tok [e * T_TOK + m] : 0;
        smul[tid] = (m < Me) ? g_mult[e * T_TOK + m] : 0.0f;
    }
    __syncthreads();

    int lr = tid >> 1;
    int lk = (tid & 1) * 4;
    int tx = tid & 15;
    int ty = tid >> 4;
    const float* Arow = A + (size_t)lr * I_DIM + lk;
    const float* Brow = B + (size_t)lr * I_DIM + lk;

    float acc[8][8];
#pragma unroll
    for (int i = 0; i < 8; ++i)
#pragma unroll
        for (int j = 0; j < 8; ++j) acc[i][j] = 0.0f;

    for (int k0 = 0; k0 < I_DIM; k0 += 8) {
        float4 a = *(const float4*)(Arow + k0);
        float4 b = *(const float4*)(Brow + k0);
        As[lk + 0][lr] = a.x; As[lk + 1][lr] = a.y;
        As[lk + 2][lr] = a.z; As[lk + 3][lr] = a.w;
        Bs[lk + 0][lr] = b.x; Bs[lk + 1][lr] = b.y;
        Bs[lk + 2][lr] = b.z; Bs[lk + 3][lr] = b.w;
        __syncthreads();
#pragma unroll
        for (int kk = 0; kk < 8; ++kk) {
            float ra[8], rb[8];
            *(float4*)(&ra[0]) = *(const float4*)(&As[kk][ty * 8]);
            *(float4*)(&ra[4]) = *(const float4*)(&As[kk][ty * 8 + 4]);
            *(float4*)(&rb[0]) = *(const float4*)(&Bs[kk][tx * 8]);
            *(float4*)(&rb[4]) = *(const float4*)(&Bs[kk][tx * 8 + 4]);
#pragma unroll
            for (int i = 0; i < 8; ++i)
#pragma unroll
                for (int j = 0; j < 8; ++j)
                    acc[i][j] += ra[i] * rb[j];
        }
        __syncthreads();
    }

    // Scatter-add with gate multiplier (exactly 2 commutative adds/element)
#pragma unroll
    for (int i = 0; i < 8; ++i) {
        int mrow = ty * 8 + i;
        int m = m0 + mrow;
        if (m < Me) {
            int   t  = stok[mrow];
            float mu = smul[mrow];
            float* dst = out + (size_t)t * H_DIM + n0 + tx * 8;
#pragma unroll
            for (int j = 0; j < 8; ++j)
                atomicAdd(dst + j, mu * acc[i][j]);
        }
    }
}

// ---------------------------------------------------------------------------
// Launch
// ---------------------------------------------------------------------------
extern "C" void kernel_launch(void* const* d_in, const int* in_sizes, int n_in,
                              void* d_out, int out_size) {
    (void)in_sizes; (void)n_in; (void)out_size;
    const float* x   = (const float*)d_in[0];   // [T, H]
    const float* gw  = (const float*)d_in[1];   // [E, H]
    const float* ws  = (const float*)d_in[2];   // [E, 2I, H]
    const float* w2s = (const float*)d_in[3];   // [E, H, I]
    float* out = (float*)d_out;                 // [T, H]

    k_init<<<(T_TOK * H_DIM + 255) / 256, 256>>>(out);
    k_router<<<T_TOK, 256>>>(x, gw);
    k_ffn1<<<dim3(T_TOK / 128, TWO_I / 128, E_EXP), 256>>>(x, ws);
    k_silu<<<dim3(I_DIM / (256 * 4), T_TOK, E_EXP), 256>>>();
    k_ffn2<<<dim3(T_TOK / 128, H_DIM / 128, E_EXP), 256>>>(w2s, out);
}

// round 5
// speedup vs baseline: 2.2232x; 2.2232x over previous
#include <cuda_runtime.h>
#include <cuda_bf16.h>
#include <math.h>
#include <stdint.h>

// Problem constants: T=1024 tokens, H=2048 hidden, I=4096 intermediate, E=8.
#define T_TOK 1024
#define H_DIM 2048
#define I_DIM 4096
#define E_EXP 8
#define TWO_I (2 * I_DIM)
#define JITTER2 0.02f   // 2 * JITTER_EPS

// ---------------------------------------------------------------------------
// Device-global scratch (allocation-free rule)
// ---------------------------------------------------------------------------
__device__ int   g_cnt[E_EXP];
__device__ int   g_tok [E_EXP * T_TOK];
__device__ float g_mult[E_EXP * T_TOK];
__device__ float g_act[(size_t)E_EXP * T_TOK * I_DIM];   // 128 MB: silu(g)*u

// ---------------------------------------------------------------------------
// Helpers: tf32 convert + m16n8k8 tf32 MMA
// ---------------------------------------------------------------------------
__device__ __forceinline__ uint32_t f2tf32(float x) {
    uint32_t r;
    asm("cvt.rna.tf32.f32 %0, %1;" : "=r"(r) : "f"(x));
    return r;
}

__device__ __forceinline__ void mma_tf32(float* c, const uint32_t* a, const uint32_t* b) {
    asm volatile(
        "mma.sync.aligned.m16n8k8.row.col.f32.tf32.tf32.f32 "
        "{%0,%1,%2,%3}, {%4,%5,%6,%7}, {%8,%9}, {%0,%1,%2,%3};"
        : "+f"(c[0]), "+f"(c[1]), "+f"(c[2]), "+f"(c[3])
        : "r"(a[0]), "r"(a[1]), "r"(a[2]), "r"(a[3]), "r"(b[0]), "r"(b[1]));
}

// ---------------------------------------------------------------------------
// Kernel 0: zero output + expert counters
// ---------------------------------------------------------------------------
__global__ void k_init(float* __restrict__ out) {
    int i = blockIdx.x * blockDim.x + threadIdx.x;
    if (i < E_EXP) g_cnt[i] = 0;
    if (i < T_TOK * H_DIM) out[i] = 0.0f;
}

// ---------------------------------------------------------------------------
// Kernel 1: router + sparsemixer + per-expert token lists (unchanged, passing)
// ---------------------------------------------------------------------------
__global__ void k_router(const float* __restrict__ x, const float* __restrict__ gw) {
    int t    = blockIdx.x;
    int warp = threadIdx.x >> 5;
    int lane = threadIdx.x & 31;

    const float4* xr = (const float4*)(x + (size_t)t * H_DIM);
    const float4* gr = (const float4*)(gw + (size_t)warp * H_DIM);

    float s = 0.0f;
    for (int i = lane; i < H_DIM / 4; i += 32) {
        float4 a = xr[i];
        float4 b = gr[i];
        s += a.x * b.x + a.y * b.y + a.z * b.z + a.w * b.w;
    }
#pragma unroll
    for (int o = 16; o > 0; o >>= 1) s += __shfl_xor_sync(0xFFFFFFFFu, s, o);

    __shared__ float sc[E_EXP];
    if (lane == 0) sc[warp] = s;
    __syncthreads();

    if (threadIdx.x == 0) {
        float sco[E_EXP];
#pragma unroll
        for (int e = 0; e < E_EXP; ++e) sco[e] = sc[e];

        float max1 = sco[0]; int ind1 = 0;
#pragma unroll
        for (int e = 1; e < E_EXP; ++e)
            if (sco[e] > max1) { max1 = sco[e]; ind1 = e; }
        float sum1 = 0.0f;
#pragma unroll
        for (int e = 0; e < E_EXP; ++e) {
            float factor = fmaxf(fabsf(sco[e]), max1);
            bool masked = (max1 - sco[e]) / factor > JITTER2;
            if (!masked) sum1 += expf(sco[e] - max1);
        }
        float mult1 = 1.0f / sum1;

        float max2 = -INFINITY; int ind2 = 0;
#pragma unroll
        for (int e = 0; e < E_EXP; ++e)
            if (e != ind1 && sco[e] > max2) { max2 = sco[e]; ind2 = e; }
        float sum2 = 0.0f;
#pragma unroll
        for (int e = 0; e < E_EXP; ++e) {
            if (e == ind1) continue;
            float factor = fmaxf(fabsf(sco[e]), max2);
            bool masked = (max2 - sco[e]) / factor > JITTER2;
            if (!masked) sum2 += expf(sco[e] - max2);
        }
        float mult2 = 1.0f / sum2;

        int p1 = atomicAdd(&g_cnt[ind1], 1);
        g_tok [ind1 * T_TOK + p1] = t;
        g_mult[ind1 * T_TOK + p1] = mult1;
        int p2 = atomicAdd(&g_cnt[ind2], 1);
        g_tok [ind2 * T_TOK + p2] = t;
        g_mult[ind2 * T_TOK + p2] = mult2;
    }
}

// ---------------------------------------------------------------------------
// tf32 MMA grouped GEMM 1 + fused SiLU.
// Block tile: M=128, two N=64 halves (gate cols n0.., up cols I+n0..), BK=16.
// 8 warps as 4(m) x 2(n); warp tile 32x32 per half.
// act[e, m, n] = silu(x@wg^T) * (x@wu^T)
// ---------------------------------------------------------------------------
#define BM 128
#define BN 64
#define BK 16
#define SA_W (BM + 8)   // padded: fragment LDS conflict-free (136 % 32 == 8)
#define SB_W (BN + 8)   // 72 % 32 == 8

__global__ __launch_bounds__(256, 1)
void k_ffn1(const float* __restrict__ x, const float* __restrict__ ws) {
    int e  = blockIdx.z;
    int Me = g_cnt[e];
    int m0 = blockIdx.x * BM;
    if (m0 >= Me) return;
    int n0 = blockIdx.y * BN;

    const float* Bg = ws + (size_t)e * TWO_I * H_DIM + (size_t)n0 * H_DIM;
    const float* Bu = Bg + (size_t)I_DIM * H_DIM;

    __shared__ uint32_t sA[BK][SA_W];
    __shared__ uint32_t sG[BK][SB_W];
    __shared__ uint32_t sU[BK][SB_W];
    __shared__ int stok[BM];

    int tid = threadIdx.x;
    if (tid < BM) {
        int m = m0 + tid;
        stok[tid] = (m < Me) ? g_tok[e * T_TOK + m] : g_tok[e * T_TOK];
    }
    __syncthreads();

    // global load indices: 4 threads per row (float4 each), rows tid>>2
    int ar0 = tid >> 2;            // 0..63
    int ar1 = ar0 + 64;            // 64..127
    int akq = (tid & 3) * 4;       // k sub-offset {0,4,8,12}
    const float* pA0 = x + (size_t)stok[ar0] * H_DIM + akq;
    const float* pA1 = x + (size_t)stok[ar1] * H_DIM + akq;
    const float* pG  = Bg + (size_t)ar0 * H_DIM + akq;
    const float* pU  = Bu + (size_t)ar0 * H_DIM + akq;

    int warp = tid >> 5, lane = tid & 31;
    int wm = (warp & 3) * 32;      // m offset of warp tile
    int wn = (warp >> 2) * 32;     // n offset of warp tile
    int tg = lane >> 2, tt = lane & 3;

    float accG[2][4][4], accU[2][4][4];
#pragma unroll
    for (int i = 0; i < 2; ++i)
#pragma unroll
        for (int j = 0; j < 4; ++j)
#pragma unroll
            for (int r = 0; r < 4; ++r) { accG[i][j][r] = 0.f; accU[i][j][r] = 0.f; }

    float4 ra0 = *(const float4*)pA0;
    float4 ra1 = *(const float4*)pA1;
    float4 rg  = *(const float4*)pG;
    float4 ru  = *(const float4*)pU;

    for (int k0 = 0; k0 < H_DIM; k0 += BK) {
        // store current tile (tf32-rounded once per element)
        sA[akq + 0][ar0] = f2tf32(ra0.x); sA[akq + 1][ar0] = f2tf32(ra0.y);
        sA[akq + 2][ar0] = f2tf32(ra0.z); sA[akq + 3][ar0] = f2tf32(ra0.w);
        sA[akq + 0][ar1] = f2tf32(ra1.x); sA[akq + 1][ar1] = f2tf32(ra1.y);
        sA[akq + 2][ar1] = f2tf32(ra1.z); sA[akq + 3][ar1] = f2tf32(ra1.w);
        sG[akq + 0][ar0] = f2tf32(rg.x);  sG[akq + 1][ar0] = f2tf32(rg.y);
        sG[akq + 2][ar0] = f2tf32(rg.z);  sG[akq + 3][ar0] = f2tf32(rg.w);
        sU[akq + 0][ar0] = f2tf32(ru.x);  sU[akq + 1][ar0] = f2tf32(ru.y);
        sU[akq + 2][ar0] = f2tf32(ru.z);  sU[akq + 3][ar0] = f2tf32(ru.w);
        __syncthreads();

        // prefetch next tile (overlaps with MMA below)
        if (k0 + BK < H_DIM) {
            ra0 = *(const float4*)(pA0 + k0 + BK);
            ra1 = *(const float4*)(pA1 + k0 + BK);
            rg  = *(const float4*)(pG + k0 + BK);
            ru  = *(const float4*)(pU + k0 + BK);
        }

#pragma unroll
        for (int ks = 0; ks < 2; ++ks) {
            int kb = ks * 8;
            uint32_t af[2][4];
#pragma unroll
            for (int mt = 0; mt < 2; ++mt) {
                int rb = wm + mt * 16;
                af[mt][0] = sA[kb + tt][rb + tg];
                af[mt][1] = sA[kb + tt][rb + tg + 8];
                af[mt][2] = sA[kb + tt + 4][rb + tg];
                af[mt][3] = sA[kb + tt + 4][rb + tg + 8];
            }
            uint32_t bgf[4][2], buf[4][2];
#pragma unroll
            for (int nt = 0; nt < 4; ++nt) {
                int nb = wn + nt * 8 + tg;
                bgf[nt][0] = sG[kb + tt][nb];     bgf[nt][1] = sG[kb + tt + 4][nb];
                buf[nt][0] = sU[kb + tt][nb];     buf[nt][1] = sU[kb + tt + 4][nb];
            }
#pragma unroll
            for (int mt = 0; mt < 2; ++mt)
#pragma unroll
                for (int nt = 0; nt < 4; ++nt) {
                    mma_tf32(accG[mt][nt], af[mt], bgf[nt]);
                    mma_tf32(accU[mt][nt], af[mt], buf[nt]);
                }
        }
        __syncthreads();
    }

    // fused SiLU epilogue: act = silu(g) * u
    float* actb = g_act + (size_t)e * T_TOK * I_DIM;
#pragma unroll
    for (int mt = 0; mt < 2; ++mt)
#pragma unroll
        for (int r = 0; r < 4; ++r) {
            int m = m0 + wm + mt * 16 + tg + ((r >= 2) ? 8 : 0);
            if (m < Me) {
#pragma unroll
                for (int nt = 0; nt < 4; ++nt) {
                    int n = n0 + wn + nt * 8 + tt * 2 + (r & 1);
                    float gv = accG[mt][nt][r];
                    float uv = accU[mt][nt][r];
                    actb[(size_t)m * I_DIM + n] = gv / (1.0f + expf(-gv)) * uv;
                }
            }
        }
}

// ---------------------------------------------------------------------------
// tf32 MMA grouped GEMM 2 + scatter: out[tok, n] += mult * (act @ w2s^T)
// Block tile: M=128, N=128 as two 64-halves (same machinery), BK=16, K=4096.
// ---------------------------------------------------------------------------
__global__ __launch_bounds__(256, 1)
void k_ffn2(const float* __restrict__ w2s, float* __restrict__ out) {
    int e  = blockIdx.z;
    int Me = g_cnt[e];
    int m0 = blockIdx.x * BM;
    if (m0 >= Me) return;
    int n0 = blockIdx.y * 128;

    const float* A  = g_act + ((size_t)e * T_TOK + m0) * I_DIM;
    const float* B0 = w2s + (size_t)e * H_DIM * I_DIM + (size_t)n0 * I_DIM;
    const float* B1 = B0 + (size_t)BN * I_DIM;

    __shared__ uint32_t sA[BK][SA_W];
    __shared__ uint32_t sG[BK][SB_W];   // cols n0..n0+63
    __shared__ uint32_t sU[BK][SB_W];   // cols n0+64..n0+127
    __shared__ int   stok[BM];
    __shared__ float smul[BM];

    int tid = threadIdx.x;
    if (tid < BM) {
        int m = m0 + tid;
        stok[tid] = (m < Me) ? g_tok [e * T_TOK + m] : 0;
        smul[tid] = (m < Me) ? g_mult[e * T_TOK + m] : 0.0f;
    }
    __syncthreads();

    int ar0 = tid >> 2;
    int ar1 = ar0 + 64;
    int akq = (tid & 3) * 4;
    const float* pA0 = A + (size_t)ar0 * I_DIM + akq;
    const float* pA1 = A + (size_t)ar1 * I_DIM + akq;
    const float* pG  = B0 + (size_t)ar0 * I_DIM + akq;
    const float* pU  = B1 + (size_t)ar0 * I_DIM + akq;

    int warp = tid >> 5, lane = tid & 31;
    int wm = (warp & 3) * 32;
    int wn = (warp >> 2) * 32;
    int tg = lane >> 2, tt = lane & 3;

    float accG[2][4][4], accU[2][4][4];
#pragma unroll
    for (int i = 0; i < 2; ++i)
#pragma unroll
        for (int j = 0; j < 4; ++j)
#pragma unroll
            for (int r = 0; r < 4; ++r) { accG[i][j][r] = 0.f; accU[i][j][r] = 0.f; }

    float4 ra0 = *(const float4*)pA0;
    float4 ra1 = *(const float4*)pA1;
    float4 rg  = *(const float4*)pG;
    float4 ru  = *(const float4*)pU;

    for (int k0 = 0; k0 < I_DIM; k0 += BK) {
        sA[akq + 0][ar0] = f2tf32(ra0.x); sA[akq + 1][ar0] = f2tf32(ra0.y);
        sA[akq + 2][ar0] = f2tf32(ra0.z); sA[akq + 3][ar0] = f2tf32(ra0.w);
        sA[akq + 0][ar1] = f2tf32(ra1.x); sA[akq + 1][ar1] = f2tf32(ra1.y);
        sA[akq + 2][ar1] = f2tf32(ra1.z); sA[akq + 3][ar1] = f2tf32(ra1.w);
        sG[akq + 0][ar0] = f2tf32(rg.x);  sG[akq + 1][ar0] = f2tf32(rg.y);
        sG[akq + 2][ar0] = f2tf32(rg.z);  sG[akq + 3][ar0] = f2tf32(rg.w);
        sU[akq + 0][ar0] = f2tf32(ru.x);  sU[akq + 1][ar0] = f2tf32(ru.y);
        sU[akq + 2][ar0] = f2tf32(ru.z);  sU[akq + 3][ar0] = f2tf32(ru.w);
        __syncthreads();

        if (k0 + BK < I_DIM) {
            ra0 = *(const float4*)(pA0 + k0 + BK);
            ra1 = *(const float4*)(pA1 + k0 + BK);
            rg  = *(const float4*)(pG + k0 + BK);
            ru  = *(const float4*)(pU + k0 + BK);
        }

#pragma unroll
        for (int ks = 0; ks < 2; ++ks) {
            int kb = ks * 8;
            uint32_t af[2][4];
#pragma unroll
            for (int mt = 0; mt < 2; ++mt) {
                int rb = wm + mt * 16;
                af[mt][0] = sA[kb + tt][rb + tg];
                af[mt][1] = sA[kb + tt][rb + tg + 8];
                af[mt][2] = sA[kb + tt + 4][rb + tg];
                af[mt][3] = sA[kb + tt + 4][rb + tg + 8];
            }
            uint32_t bgf[4][2], buf[4][2];
#pragma unroll
            for (int nt = 0; nt < 4; ++nt) {
                int nb = wn + nt * 8 + tg;
                bgf[nt][0] = sG[kb + tt][nb];     bgf[nt][1] = sG[kb + tt + 4][nb];
                buf[nt][0] = sU[kb + tt][nb];     buf[nt][1] = sU[kb + tt + 4][nb];
            }
#pragma unroll
            for (int mt = 0; mt < 2; ++mt)
#pragma unroll
                for (int nt = 0; nt < 4; ++nt) {
                    mma_tf32(accG[mt][nt], af[mt], bgf[nt]);
                    mma_tf32(accU[mt][nt], af[mt], buf[nt]);
                }
        }
        __syncthreads();
    }

    // scatter epilogue: out[tok, n] += mult * c   (2 commutative adds/elem)
#pragma unroll
    for (int mt = 0; mt < 2; ++mt)
#pragma unroll
        for (int r = 0; r < 4; ++r) {
            int mrow = wm + mt * 16 + tg + ((r >= 2) ? 8 : 0);
            int m = m0 + mrow;
            if (m < Me) {
                int   t  = stok[mrow];
                float mu = smul[mrow];
                float* dst = out + (size_t)t * H_DIM;
#pragma unroll
                for (int nt = 0; nt < 4; ++nt) {
                    int nc = wn + nt * 8 + tt * 2 + (r & 1);
                    atomicAdd(dst + n0 + nc,      mu * accG[mt][nt][r]);
                    atomicAdd(dst + n0 + 64 + nc, mu * accU[mt][nt][r]);
                }
            }
        }
}

// ---------------------------------------------------------------------------
// Launch
// ---------------------------------------------------------------------------
extern "C" void kernel_launch(void* const* d_in, const int* in_sizes, int n_in,
                              void* d_out, int out_size) {
    (void)in_sizes; (void)n_in; (void)out_size;
    const float* x   = (const float*)d_in[0];   // [T, H]
    const float* gw  = (const float*)d_in[1];   // [E, H]
    const float* ws  = (const float*)d_in[2];   // [E, 2I, H]
    const float* w2s = (const float*)d_in[3];   // [E, H, I]
    float* out = (float*)d_out;                 // [T, H]

    k_init<<<(T_TOK * H_DIM + 255) / 256, 256>>>(out);
    k_router<<<T_TOK, 256>>>(x, gw);
    k_ffn1<<<dim3(T_TOK / BM, I_DIM / BN, E_EXP), 256>>>(x, ws);
    k_ffn2<<<dim3(T_TOK / BM, H_DIM / 128, E_EXP), 256>>>(w2s, out);
}

// round 6
// speedup vs baseline: 2.8622x; 1.2874x over previous
#include <cuda_runtime.h>
#include <cuda_bf16.h>
#include <math.h>
#include <stdint.h>

// Problem constants: T=1024 tokens, H=2048 hidden, I=4096 intermediate, E=8.
#define T_TOK 1024
#define H_DIM 2048
#define I_DIM 4096
#define E_EXP 8
#define TWO_I (2 * I_DIM)
#define JITTER2 0.02f   // 2 * JITTER_EPS

// GEMM tiling
#define RS   20              // smem row stride in floats (conflict-free for frag LDS)
#define MATF (128 * RS)      // floats per matrix tile per stage (2560)
#define NSTG 3               // cp.async pipeline stages
#define SMEMB (NSTG * MATF * 3 * 4)   // 92160 bytes dynamic smem

// ---------------------------------------------------------------------------
// Device-global scratch (allocation-free rule)
// ---------------------------------------------------------------------------
__device__ int   g_cnt[E_EXP];
__device__ int   g_tok [E_EXP * T_TOK];
__device__ float g_mult[E_EXP * T_TOK];
__device__ float g_act[(size_t)E_EXP * T_TOK * I_DIM];   // 128 MB: silu(g)*u

// ---------------------------------------------------------------------------
// Helpers
// ---------------------------------------------------------------------------
__device__ __forceinline__ uint32_t f2tf32(float x) {
    uint32_t r;
    asm("cvt.rna.tf32.f32 %0, %1;" : "=r"(r) : "f"(x));
    return r;
}

__device__ __forceinline__ void mma_tf32(float* c, const uint32_t* a, const uint32_t* b) {
    asm volatile(
        "mma.sync.aligned.m16n8k8.row.col.f32.tf32.tf32.f32 "
        "{%0,%1,%2,%3}, {%4,%5,%6,%7}, {%8,%9}, {%0,%1,%2,%3};"
        : "+f"(c[0]), "+f"(c[1]), "+f"(c[2]), "+f"(c[3])
        : "r"(a[0]), "r"(a[1]), "r"(a[2]), "r"(a[3]), "r"(b[0]), "r"(b[1]));
}

__device__ __forceinline__ void cp16(uint32_t dst, const void* src) {
    asm volatile("cp.async.cg.shared.global [%0], [%1], 16;" :: "r"(dst), "l"(src) : "memory");
}
#define CP_COMMIT() asm volatile("cp.async.commit_group;" ::: "memory")
#define CP_WAIT2()  asm volatile("cp.async.wait_group 2;" ::: "memory")
#define CP_WAIT0()  asm volatile("cp.async.wait_group 0;" ::: "memory")

// ---------------------------------------------------------------------------
// Kernel 0: zero output + expert counters
// ---------------------------------------------------------------------------
__global__ void k_init(float* __restrict__ out) {
    int i = blockIdx.x * blockDim.x + threadIdx.x;
    if (i < E_EXP) g_cnt[i] = 0;
    if (i < T_TOK * H_DIM) out[i] = 0.0f;
}

// ---------------------------------------------------------------------------
// Kernel 1: router + sparsemixer + per-expert token lists
// ---------------------------------------------------------------------------
__global__ void k_router(const float* __restrict__ x, const float* __restrict__ gw) {
    int t    = blockIdx.x;
    int warp = threadIdx.x >> 5;
    int lane = threadIdx.x & 31;

    const float4* xr = (const float4*)(x + (size_t)t * H_DIM);
    const float4* gr = (const float4*)(gw + (size_t)warp * H_DIM);

    float s = 0.0f;
    for (int i = lane; i < H_DIM / 4; i += 32) {
        float4 a = xr[i];
        float4 b = gr[i];
        s += a.x * b.x + a.y * b.y + a.z * b.z + a.w * b.w;
    }
#pragma unroll
    for (int o = 16; o > 0; o >>= 1) s += __shfl_xor_sync(0xFFFFFFFFu, s, o);

    __shared__ float sc[E_EXP];
    if (lane == 0) sc[warp] = s;
    __syncthreads();

    if (threadIdx.x == 0) {
        float sco[E_EXP];
#pragma unroll
        for (int e = 0; e < E_EXP; ++e) sco[e] = sc[e];

        float max1 = sco[0]; int ind1 = 0;
#pragma unroll
        for (int e = 1; e < E_EXP; ++e)
            if (sco[e] > max1) { max1 = sco[e]; ind1 = e; }
        float sum1 = 0.0f;
#pragma unroll
        for (int e = 0; e < E_EXP; ++e) {
            float factor = fmaxf(fabsf(sco[e]), max1);
            bool masked = (max1 - sco[e]) / factor > JITTER2;
            if (!masked) sum1 += expf(sco[e] - max1);
        }
        float mult1 = 1.0f / sum1;

        float max2 = -INFINITY; int ind2 = 0;
#pragma unroll
        for (int e = 0; e < E_EXP; ++e)
            if (e != ind1 && sco[e] > max2) { max2 = sco[e]; ind2 = e; }
        float sum2 = 0.0f;
#pragma unroll
        for (int e = 0; e < E_EXP; ++e) {
            if (e == ind1) continue;
            float factor = fmaxf(fabsf(sco[e]), max2);
            bool masked = (max2 - sco[e]) / factor > JITTER2;
            if (!masked) sum2 += expf(sco[e] - max2);
        }
        float mult2 = 1.0f / sum2;

        int p1 = atomicAdd(&g_cnt[ind1], 1);
        g_tok [ind1 * T_TOK + p1] = t;
        g_mult[ind1 * T_TOK + p1] = mult1;
        int p2 = atomicAdd(&g_cnt[ind2], 1);
        g_tok [ind2 * T_TOK + p2] = t;
        g_mult[ind2 * T_TOK + p2] = mult2;
    }
}

// ---------------------------------------------------------------------------
// Shared GEMM mainloop body (macro): 3-stage cp.async pipeline, warp 64x32
// tiles for G and U halves, tf32 cvt at fragment load.
// Requires in scope: SA,SG,SU (float*), dA,dG,dU (u32 smem addrs), gA,gG,gU
// (global ptrs), NT, wm, wn, tg, tt, accG, accU.
// ---------------------------------------------------------------------------
#define ISSUE_TILE(t)                                                          \
    do {                                                                       \
        int _st = (t) % NSTG; int _ko = (t) * 16;                              \
        uint32_t _so = (uint32_t)_st * (MATF * 4);                             \
        cp16(dA + _so,      gA + _ko);     cp16(dA + _so + 16, gA + _ko + 4);  \
        cp16(dG + _so,      gG + _ko);     cp16(dG + _so + 16, gG + _ko + 4);  \
        cp16(dU + _so,      gU + _ko);     cp16(dU + _so + 16, gU + _ko + 4);  \
        CP_COMMIT();                                                           \
    } while (0)

#define GEMM_MAINLOOP()                                                        \
    ISSUE_TILE(0);                                                             \
    ISSUE_TILE(1);                                                             \
    for (int t = 0; t < NT; ++t) {                                             \
        if (t + 2 < NT) { ISSUE_TILE(t + 2); CP_WAIT2(); }                     \
        else            { CP_WAIT0(); }                                        \
        __syncthreads();                                                       \
        const float* A = SA + (t % NSTG) * MATF;                               \
        const float* G = SG + (t % NSTG) * MATF;                               \
        const float* U = SU + (t % NSTG) * MATF;                               \
        _Pragma("unroll")                                                      \
        for (int ks = 0; ks < 2; ++ks) {                                       \
            int kb = ks * 8;                                                   \
            uint32_t af[4][4];                                                 \
            _Pragma("unroll")                                                  \
            for (int mt = 0; mt < 4; ++mt) {                                   \
                int rb = wm + mt * 16;                                         \
                af[mt][0] = f2tf32(A[(rb + tg)     * RS + kb + tt]);           \
                af[mt][1] = f2tf32(A[(rb + tg + 8) * RS + kb + tt]);           \
                af[mt][2] = f2tf32(A[(rb + tg)     * RS + kb + tt + 4]);       \
                af[mt][3] = f2tf32(A[(rb + tg + 8) * RS + kb + tt + 4]);       \
            }                                                                  \
            uint32_t bg[4][2], bu[4][2];                                       \
            _Pragma("unroll")                                                  \
            for (int nt = 0; nt < 4; ++nt) {                                   \
                int nb = (wn + nt * 8 + tg) * RS + kb;                         \
                bg[nt][0] = f2tf32(G[nb + tt]);                                \
                bg[nt][1] = f2tf32(G[nb + tt + 4]);                            \
                bu[nt][0] = f2tf32(U[nb + tt]);                                \
                bu[nt][1] = f2tf32(U[nb + tt + 4]);                            \
            }                                                                  \
            _Pragma("unroll")                                                  \
            for (int mt = 0; mt < 4; ++mt)                                     \
                _Pragma("unroll")                                              \
                for (int nt = 0; nt < 4; ++nt) {                               \
                    mma_tf32(accG[mt][nt], af[mt], bg[nt]);                    \
                    mma_tf32(accU[mt][nt], af[mt], bu[nt]);                    \
                }                                                              \
        }                                                                      \
        __syncthreads();                                                       \
    }

// ---------------------------------------------------------------------------
// GEMM 1 + fused SiLU: act[e,m,n] = silu(x@wg^T) * (x@wu^T)
// Block: 128 rows x 128 paired cols (gate n0.., up I+n0..). 8 warps 2m x 4n,
// warp tile 64x32 per half. K = H_DIM.
// ---------------------------------------------------------------------------
__global__ __launch_bounds__(256, 1)
void k_ffn1(const float* __restrict__ x, const float* __restrict__ ws) {
    int e  = blockIdx.z;
    int Me = g_cnt[e];
    int m0 = blockIdx.x * 128;
    if (m0 >= Me) return;
    int n0 = blockIdx.y * 128;

    extern __shared__ float sm[];
    float* SA = sm;
    float* SG = sm + NSTG * MATF;
    float* SU = sm + 2 * NSTG * MATF;
    __shared__ int stok[128];

    int tid = threadIdx.x;
    if (tid < 128) {
        int m = m0 + tid;
        stok[tid] = (m < Me) ? g_tok[e * T_TOK + m] : g_tok[e * T_TOK];
    }
    __syncthreads();

    int lr = tid >> 1, lc = (tid & 1) * 8;
    const float* gA = x + (size_t)stok[lr] * H_DIM + lc;
    const float* gG = ws + (size_t)e * TWO_I * H_DIM + (size_t)(n0 + lr) * H_DIM + lc;
    const float* gU = gG + (size_t)I_DIM * H_DIM;
    uint32_t ro = (uint32_t)(lr * RS + lc) * 4;
    uint32_t dA = (uint32_t)__cvta_generic_to_shared(SA) + ro;
    uint32_t dG = (uint32_t)__cvta_generic_to_shared(SG) + ro;
    uint32_t dU = (uint32_t)__cvta_generic_to_shared(SU) + ro;

    int warp = tid >> 5, lane = tid & 31;
    int wm = (warp & 1) * 64, wn = (warp >> 1) * 32;
    int tg = lane >> 2, tt = lane & 3;

    float accG[4][4][4], accU[4][4][4];
#pragma unroll
    for (int i = 0; i < 4; ++i)
#pragma unroll
        for (int j = 0; j < 4; ++j)
#pragma unroll
            for (int r = 0; r < 4; ++r) { accG[i][j][r] = 0.f; accU[i][j][r] = 0.f; }

    const int NT = H_DIM / 16;
    GEMM_MAINLOOP();

    // fused SiLU epilogue
    float* actb = g_act + (size_t)e * T_TOK * I_DIM;
#pragma unroll
    for (int mt = 0; mt < 4; ++mt)
#pragma unroll
        for (int r = 0; r < 4; ++r) {
            int m = m0 + wm + mt * 16 + tg + ((r >= 2) ? 8 : 0);
            if (m < Me) {
#pragma unroll
                for (int nt = 0; nt < 4; ++nt) {
                    int n = n0 + wn + nt * 8 + tt * 2 + (r & 1);
                    float gv = accG[mt][nt][r];
                    float uv = accU[mt][nt][r];
                    actb[(size_t)m * I_DIM + n] = gv / (1.0f + expf(-gv)) * uv;
                }
            }
        }
}

// ---------------------------------------------------------------------------
// GEMM 2 + scatter: out[tok,n] += mult * (act @ w2s^T)
// Block: 128 rows x 256 cols (two 128 halves), K-split x2.
// blockIdx.y: bit0 = k-split, bits>0 = n-tile (H/256 = 8).
// ---------------------------------------------------------------------------
__global__ __launch_bounds__(256, 1)
void k_ffn2(const float* __restrict__ w2s, float* __restrict__ out) {
    int e  = blockIdx.z;
    int Me = g_cnt[e];
    int m0 = blockIdx.x * 128;
    if (m0 >= Me) return;
    int n0 = (blockIdx.y >> 1) * 256;
    int kb0 = (blockIdx.y & 1) * (I_DIM / 2);

    extern __shared__ float sm[];
    float* SA = sm;
    float* SG = sm + NSTG * MATF;        // cols n0..n0+127
    float* SU = sm + 2 * NSTG * MATF;    // cols n0+128..n0+255
    __shared__ int   stok[128];
    __shared__ float smul[128];

    int tid = threadIdx.x;
    if (tid < 128) {
        int m = m0 + tid;
        stok[tid] = (m < Me) ? g_tok [e * T_TOK + m] : 0;
        smul[tid] = (m < Me) ? g_mult[e * T_TOK + m] : 0.0f;
    }
    __syncthreads();

    int lr = tid >> 1, lc = (tid & 1) * 8;
    const float* gA = g_act + ((size_t)e * T_TOK + m0 + lr) * I_DIM + kb0 + lc;
    const float* gG = w2s + (size_t)e * H_DIM * I_DIM + (size_t)(n0 + lr) * I_DIM + kb0 + lc;
    const float* gU = gG + (size_t)128 * I_DIM;
    uint32_t ro = (uint32_t)(lr * RS + lc) * 4;
    uint32_t dA = (uint32_t)__cvta_generic_to_shared(SA) + ro;
    uint32_t dG = (uint32_t)__cvta_generic_to_shared(SG) + ro;
    uint32_t dU = (uint32_t)__cvta_generic_to_shared(SU) + ro;

    int warp = tid >> 5, lane = tid & 31;
    int wm = (warp & 1) * 64, wn = (warp >> 1) * 32;
    int tg = lane >> 2, tt = lane & 3;

    float accG[4][4][4], accU[4][4][4];
#pragma unroll
    for (int i = 0; i < 4; ++i)
#pragma unroll
        for (int j = 0; j < 4; ++j)
#pragma unroll
            for (int r = 0; r < 4; ++r) { accG[i][j][r] = 0.f; accU[i][j][r] = 0.f; }

    const int NT = (I_DIM / 2) / 16;
    GEMM_MAINLOOP();

    // scatter epilogue: out[tok, n] += mult * c  (4 commutative adds/elem)
#pragma unroll
    for (int mt = 0; mt < 4; ++mt)
#pragma unroll
        for (int r = 0; r < 4; ++r) {
            int ml = wm + mt * 16 + tg + ((r >= 2) ? 8 : 0);
            int m = m0 + ml;
            if (m < Me) {
                int   t  = stok[ml];
                float mu = smul[ml];
                float* dst = out + (size_t)t * H_DIM + n0;
#pragma unroll
                for (int nt = 0; nt < 4; ++nt) {
                    int c = wn + nt * 8 + tt * 2 + (r & 1);
                    atomicAdd(dst + c,       mu * accG[mt][nt][r]);
                    atomicAdd(dst + 128 + c, mu * accU[mt][nt][r]);
                }
            }
        }
}

// ---------------------------------------------------------------------------
// Launch
// ---------------------------------------------------------------------------
extern "C" void kernel_launch(void* const* d_in, const int* in_sizes, int n_in,
                              void* d_out, int out_size) {
    (void)in_sizes; (void)n_in; (void)out_size;
    const float* x   = (const float*)d_in[0];   // [T, H]
    const float* gw  = (const float*)d_in[1];   // [E, H]
    const float* ws  = (const float*)d_in[2];   // [E, 2I, H]
    const float* w2s = (const float*)d_in[3];   // [E, H, I]
    float* out = (float*)d_out;                 // [T, H]

    cudaFuncSetAttribute(k_ffn1, cudaFuncAttributeMaxDynamicSharedMemorySize, SMEMB);
    cudaFuncSetAttribute(k_ffn2, cudaFuncAttributeMaxDynamicSharedMemorySize, SMEMB);

    k_init<<<(T_TOK * H_DIM + 255) / 256, 256>>>(out);
    k_router<<<T_TOK, 256>>>(x, gw);
    k_ffn1<<<dim3(T_TOK / 128, I_DIM / 128, E_EXP), 256, SMEMB>>>(x, ws);
    k_ffn2<<<dim3(T_TOK / 128, (H_DIM / 256) * 2, E_EXP), 256, SMEMB>>>(w2s, out);
}

// round 8
// speedup vs baseline: 3.6865x; 1.2880x over previous
#include <cuda_runtime.h>
#include <math.h>
#include <stdint.h>

// Problem constants: T=1024 tokens, H=2048 hidden, I=4096 intermediate, E=8.
#define T_TOK 1024
#define H_DIM 2048
#define I_DIM 4096
#define E_EXP 8
#define TWO_I (2 * I_DIM)
#define JITTER2 0.02f   // 2 * JITTER_EPS

// GEMM tiling: CTA tile M=128 x N=256 (two 128-halves), BK=32 floats (=128B rows).
#define BKF     32
#define A_STG_B 16384                       // 128 rows * 128 B
#define B_STG_B 32768                       // 256 rows * 128 B
#define NSTG    3
#define SB_OFF  (NSTG * A_STG_B)            // 49152
#define SMEMB   (NSTG * (A_STG_B + B_STG_B) + 1024)   // 148480 (align pad)

// ---------------------------------------------------------------------------
// Device-global scratch (allocation-free rule)
// ---------------------------------------------------------------------------
__device__ int   g_cnt[E_EXP];
__device__ int   g_tok [E_EXP * T_TOK];
__device__ float g_mult[E_EXP * T_TOK];
__device__ __align__(128) float g_xr [(size_t)T_TOK * H_DIM];           // tf32-rounded x
__device__ __align__(128) float g_act[(size_t)E_EXP * T_TOK * I_DIM];   // silu(g)*u, rounded

// ---------------------------------------------------------------------------
// Helpers
// ---------------------------------------------------------------------------
__device__ __forceinline__ uint32_t f2tf32(float x) {
    uint32_t r;
    asm("cvt.rna.tf32.f32 %0, %1;" : "=r"(r) : "f"(x));
    return r;
}
__device__ __forceinline__ float rna(float x) { return __uint_as_float(f2tf32(x)); }

__device__ __forceinline__ void mma_tf32(float* c, const uint32_t* a, const uint32_t* b) {
    asm volatile(
        "mma.sync.aligned.m16n8k8.row.col.f32.tf32.tf32.f32 "
        "{%0,%1,%2,%3}, {%4,%5,%6,%7}, {%8,%9}, {%0,%1,%2,%3};"
        : "+f"(c[0]), "+f"(c[1]), "+f"(c[2]), "+f"(c[3])
        : "r"(a[0]), "r"(a[1]), "r"(a[2]), "r"(a[3]), "r"(b[0]), "r"(b[1]));
}

// ldmatrix x4 (b16) — used to load tf32 fragments (8x4-f32 == 8x8-b16 trick)
__device__ __forceinline__ void ldsm4(uint32_t* r, uint32_t addr) {
    asm volatile(
        "ldmatrix.sync.aligned.m8n8.x4.shared.b16 {%0,%1,%2,%3}, [%4];"
        : "=r"(r[0]), "=r"(r[1]), "=r"(r[2]), "=r"(r[3]) : "r"(addr));
}

__device__ __forceinline__ void cp16(uint32_t dst, const void* src) {
    asm volatile("cp.async.cg.shared.global [%0], [%1], 16;" :: "r"(dst), "l"(src) : "memory");
}
#define CP_COMMIT() asm volatile("cp.async.commit_group;" ::: "memory")
#define CP_WAIT(n)  asm volatile("cp.async.wait_group %0;" :: "n"(n) : "memory")

// ---------------------------------------------------------------------------
// Kernel 0: zero output + expert counters
// ---------------------------------------------------------------------------
__global__ void k_init(float* __restrict__ out) {
    int i = blockIdx.x * blockDim.x + threadIdx.x;
    if (i < E_EXP) g_cnt[i] = 0;
    if (i < T_TOK * H_DIM) out[i] = 0.0f;
}

// Pre-round x to tf32 (A-side of ffn1 needs no cvt in the mainloop)
__global__ void k_round_x(const float* __restrict__ x) {
    int i = blockIdx.x * blockDim.x + threadIdx.x;   // float4 index
    float4 v = ((const float4*)x)[i];
    v.x = rna(v.x); v.y = rna(v.y); v.z = rna(v.z); v.w = rna(v.w);
    ((float4*)g_xr)[i] = v;
}

// ---------------------------------------------------------------------------
// Kernel 1: router + sparsemixer + per-expert token lists (unchanged, passing)
// ---------------------------------------------------------------------------
__global__ void k_router(const float* __restrict__ x, const float* __restrict__ gw) {
    int t    = blockIdx.x;
    int warp = threadIdx.x >> 5;
    int lane = threadIdx.x & 31;

    const float4* xr = (const float4*)(x + (size_t)t * H_DIM);
    const float4* gr = (const float4*)(gw + (size_t)warp * H_DIM);

    float s = 0.0f;
    for (int i = lane; i < H_DIM / 4; i += 32) {
        float4 a = xr[i];
        float4 b = gr[i];
        s += a.x * b.x + a.y * b.y + a.z * b.z + a.w * b.w;
    }
#pragma unroll
    for (int o = 16; o > 0; o >>= 1) s += __shfl_xor_sync(0xFFFFFFFFu, s, o);

    __shared__ float sc[E_EXP];
    if (lane == 0) sc[warp] = s;
    __syncthreads();

    if (threadIdx.x == 0) {
        float sco[E_EXP];
#pragma unroll
        for (int e = 0; e < E_EXP; ++e) sco[e] = sc[e];

        float max1 = sco[0]; int ind1 = 0;
#pragma unroll
        for (int e = 1; e < E_EXP; ++e)
            if (sco[e] > max1) { max1 = sco[e]; ind1 = e; }
        float sum1 = 0.0f;
#pragma unroll
        for (int e = 0; e < E_EXP; ++e) {
            float factor = fmaxf(fabsf(sco[e]), max1);
            bool masked = (max1 - sco[e]) / factor > JITTER2;
            if (!masked) sum1 += expf(sco[e] - max1);
        }
        float mult1 = 1.0f / sum1;

        float max2 = -INFINITY; int ind2 = 0;
#pragma unroll
        for (int e = 0; e < E_EXP; ++e)
            if (e != ind1 && sco[e] > max2) { max2 = sco[e]; ind2 = e; }
        float sum2 = 0.0f;
#pragma unroll
        for (int e = 0; e < E_EXP; ++e) {
            if (e == ind1) continue;
            float factor = fmaxf(fabsf(sco[e]), max2);
            bool masked = (max2 - sco[e]) / factor > JITTER2;
            if (!masked) sum2 += expf(sco[e] - max2);
        }
        float mult2 = 1.0f / sum2;

        int p1 = atomicAdd(&g_cnt[ind1], 1);
        g_tok [ind1 * T_TOK + p1] = t;
        g_mult[ind1 * T_TOK + p1] = mult1;
        int p2 = atomicAdd(&g_cnt[ind2], 1);
        g_tok [ind2 * T_TOK + p2] = t;
        g_mult[ind2 * T_TOK + p2] = mult2;
    }
}

// ---------------------------------------------------------------------------
// Mainloop pieces. SW128-style XOR swizzle: float4-chunk c of row r lives at
// r*128 + ((c ^ (r&7))<<4). ldmatrix phases & cp.async are conflict-free.
// Requires in scope: smem_u32, smf, tid, pA[4],dA[4], pB[8],dB[8].
// ---------------------------------------------------------------------------
#define ISSUE_T(j)                                                              \
    do {                                                                        \
        int _s = (j) % NSTG; int _ko = (j) * BKF;                               \
        uint32_t _ab = smem_u32 + _s * A_STG_B;                                 \
        uint32_t _bb = smem_u32 + SB_OFF + _s * B_STG_B;                        \
        _Pragma("unroll") for (int q = 0; q < 4; ++q) cp16(_ab + dA[q], pA[q] + _ko); \
        _Pragma("unroll") for (int q = 0; q < 8; ++q) cp16(_bb + dB[q], pB[q] + _ko); \
        CP_COMMIT();                                                            \
    } while (0)

#define ROUND_B(j)                                                              \
    do {                                                                        \
        int _s = (j) % NSTG;                                                    \
        char* _bb = smf + SB_OFF + _s * B_STG_B;                                \
        _Pragma("unroll") for (int q = 0; q < 8; ++q) {                         \
            float4* _p = (float4*)(_bb + dB[q]);                                \
            float4 _v = *_p;                                                    \
            _v.x = rna(_v.x); _v.y = rna(_v.y);                                 \
            _v.z = rna(_v.z); _v.w = rna(_v.w);                                 \
            *_p = _v;                                                           \
        }                                                                       \
    } while (0)

// Fragment compute for one k32 stage. A rows 128, B halves G/U 128 rows each.
#define COMPUTE_STAGE(stg)                                                      \
    do {                                                                        \
        uint32_t aS = smem_u32 + (stg) * A_STG_B;                               \
        uint32_t gS = smem_u32 + SB_OFF + (stg) * B_STG_B;                      \
        uint32_t uS = gS + 128 * 128;                                           \
        _Pragma("unroll")                                                       \
        for (int ks = 0; ks < 4; ++ks) {                                        \
            uint32_t af[4][4], bgf[2][4], buf[2][4];                            \
            _Pragma("unroll")                                                   \
            for (int mt = 0; mt < 4; ++mt)                                      \
                ldsm4(af[mt], aS + rowOffA[mt] +                                \
                      ((uint32_t)((2 * ks + lhi) ^ swA[mt]) << 4));             \
            _Pragma("unroll")                                                   \
            for (int p = 0; p < 2; ++p) {                                       \
                uint32_t ch = (uint32_t)((2 * ks + q1) ^ swB[p]) << 4;          \
                ldsm4(bgf[p], gS + rowOffB[p] + ch);                            \
                ldsm4(buf[p], uS + rowOffB[p] + ch);                            \
            }                                                                   \
            _Pragma("unroll")                                                   \
            for (int mt = 0; mt < 4; ++mt)                                      \
                _Pragma("unroll")                                               \
                for (int p = 0; p < 2; ++p) {                                   \
                    mma_tf32(accG[mt][2 * p],     af[mt], &bgf[p][0]);          \
                    mma_tf32(accG[mt][2 * p + 1], af[mt], &bgf[p][2]);          \
                    mma_tf32(accU[mt][2 * p],     af[mt], &buf[p][0]);          \
                    mma_tf32(accU[mt][2 * p + 1], af[mt], &buf[p][2]);          \
                }                                                               \
        }                                                                       \
    } while (0)

#define GEMM_MAINLOOP(NT)                                                       \
    ISSUE_T(0); ISSUE_T(1);                                                     \
    for (int t = 0; t < (NT); ++t) {                                            \
        if (t + 2 < (NT)) { ISSUE_T(t + 2); CP_WAIT(2); } else { CP_WAIT(0); }  \
        __syncthreads();                                                        \
        ROUND_B(t);                                                             \
        __syncthreads();                                                        \
        COMPUTE_STAGE(t % NSTG);                                                \
        __syncthreads();                                                        \
    }

// Per-warp/lane fragment index setup (shared by both GEMMs)
#define FRAG_SETUP()                                                            \
    int warp = tid >> 5, lane = tid & 31;                                       \
    int wm = (warp & 1) * 64, wn = (warp >> 1) * 32;                            \
    int tg = lane >> 2, tt = lane & 3;                                          \
    int l16 = lane & 15, lhi = lane >> 4, q1 = (lane >> 3) & 1;                 \
    uint32_t rowOffA[4], swA[4], rowOffB[2], swB[2];                            \
    _Pragma("unroll")                                                           \
    for (int mt = 0; mt < 4; ++mt) {                                            \
        int r = wm + mt * 16 + l16;                                             \
        rowOffA[mt] = (uint32_t)r * 128; swA[mt] = (uint32_t)(r & 7);           \
    }                                                                           \
    _Pragma("unroll")                                                           \
    for (int p = 0; p < 2; ++p) {                                               \
        int r = wn + p * 16 + ((lane >> 4) << 3) + (lane & 7);                  \
        rowOffB[p] = (uint32_t)r * 128; swB[p] = (uint32_t)(r & 7);             \
    }                                                                           \
    float accG[4][4][4], accU[4][4][4];                                         \
    _Pragma("unroll")                                                           \
    for (int i = 0; i < 4; ++i)                                                 \
        _Pragma("unroll")                                                       \
        for (int j = 0; j < 4; ++j)                                             \
            _Pragma("unroll")                                                   \
            for (int r = 0; r < 4; ++r) { accG[i][j][r] = 0.f; accU[i][j][r] = 0.f; }

// ---------------------------------------------------------------------------
// GEMM 1 + fused SiLU: act[e,m,n] = rna(silu(x@wg^T) * (x@wu^T))
// CTA: 128 tokens x (128 gate cols n0.. + 128 up cols I+n0..). K = H = 2048.
// ---------------------------------------------------------------------------
__global__ __launch_bounds__(256, 1)
void k_ffn1(const float* __restrict__ ws) {
    int e  = blockIdx.z;
    int Me = g_cnt[e];
    int m0 = blockIdx.x * 128;
    if (m0 >= Me) return;
    int n0 = blockIdx.y * 128;

    extern __shared__ float sm_raw[];
    uint32_t raw_u32  = (uint32_t)__cvta_generic_to_shared(sm_raw);
    uint32_t smem_u32 = (raw_u32 + 1023) & ~1023u;
    char* smf = (char*)sm_raw + (smem_u32 - raw_u32);
    __shared__ int stok[128];

    int tid = threadIdx.x;
    if (tid < 128) {
        int m = m0 + tid;
        stok[tid] = (m < Me) ? g_tok[e * T_TOK + m] : g_tok[e * T_TOK];
    }
    __syncthreads();

    // cp.async assignments: A 4 chunks/thread, B 8 chunks/thread
    const float* pA[4]; uint32_t dA[4];
#pragma unroll
    for (int q = 0; q < 4; ++q) {
        int a = q * 256 + tid, r = a >> 3, c = a & 7;
        pA[q] = g_xr + (size_t)stok[r] * H_DIM + c * 4;
        dA[q] = r * 128 + ((c ^ (r & 7)) << 4);
    }
    const float* pB[8]; uint32_t dB[8];
    const float* wbase = ws + (size_t)e * TWO_I * H_DIM;
#pragma unroll
    for (int q = 0; q < 8; ++q) {
        int b = q * 256 + tid, r = b >> 3, c = b & 7;
        int rowg = (r < 128) ? (n0 + r) : (I_DIM + n0 + (r - 128));
        pB[q] = wbase + (size_t)rowg * H_DIM + c * 4;
        dB[q] = r * 128 + ((c ^ (r & 7)) << 4);
    }

    FRAG_SETUP();
    GEMM_MAINLOOP(H_DIM / BKF);

    // epilogue: act = rna(silu(g) * u), float2 stores
    float* actb = g_act + (size_t)e * T_TOK * I_DIM + n0;
#pragma unroll
    for (int mt = 0; mt < 4; ++mt)
#pragma unroll
        for (int rp = 0; rp < 2; ++rp) {
            int m = m0 + wm + mt * 16 + tg + rp * 8;
            if (m < Me) {
                float* arow = actb + (size_t)m * I_DIM;
#pragma unroll
                for (int nt = 0; nt < 4; ++nt) {
                    int col = wn + nt * 8 + tt * 2;
                    float g0 = accG[mt][nt][rp * 2], g1 = accG[mt][nt][rp * 2 + 1];
                    float u0 = accU[mt][nt][rp * 2], u1 = accU[mt][nt][rp * 2 + 1];
                    float2 v;
                    v.x = rna(g0 / (1.0f + expf(-g0)) * u0);
                    v.y = rna(g1 / (1.0f + expf(-g1)) * u1);
                    *(float2*)(arow + col) = v;
                }
            }
        }
}

// ---------------------------------------------------------------------------
// GEMM 2 + scatter: out[tok,n] += mult * (act @ w2s^T)
// CTA: 128 rows x 256 out cols, K-split x2 (blockIdx.y bit0).
// ---------------------------------------------------------------------------
__global__ __launch_bounds__(256, 1)
void k_ffn2(const float* __restrict__ w2s, float* __restrict__ out) {
    int e  = blockIdx.z;
    int Me = g_cnt[e];
    int m0 = blockIdx.x * 128;
    if (m0 >= Me) return;
    int n0  = (blockIdx.y >> 1) * 256;
    int kb0 = (blockIdx.y & 1) * (I_DIM / 2);

    extern __shared__ float sm_raw[];
    uint32_t raw_u32  = (uint32_t)__cvta_generic_to_shared(sm_raw);
    uint32_t smem_u32 = (raw_u32 + 1023) & ~1023u;
    char* smf = (char*)sm_raw + (smem_u32 - raw_u32);

    int tid = threadIdx.x;

    const float* pA[4]; uint32_t dA[4];
    const float* abase = g_act + ((size_t)e * T_TOK + m0) * I_DIM + kb0;
#pragma unroll
    for (int q = 0; q < 4; ++q) {
        int a = q * 256 + tid, r = a >> 3, c = a & 7;
        pA[q] = abase + (size_t)r * I_DIM + c * 4;
        dA[q] = r * 128 + ((c ^ (r & 7)) << 4);
    }
    const float* pB[8]; uint32_t dB[8];
    const float* wbase = w2s + (size_t)e * H_DIM * I_DIM + kb0;
#pragma unroll
    for (int q = 0; q < 8; ++q) {
        int b = q * 256 + tid, r = b >> 3, c = b & 7;
        pB[q] = wbase + (size_t)(n0 + r) * I_DIM + c * 4;
        dB[q] = r * 128 + ((c ^ (r & 7)) << 4);
    }

    FRAG_SETUP();
    GEMM_MAINLOOP((I_DIM / 2) / BKF);

    // scatter epilogue: out[tok, n] += mult * v  (commutative adds)
#pragma unroll
    for (int mt = 0; mt < 4; ++mt)
#pragma unroll
        for (int rp = 0; rp < 2; ++rp) {
            int ml = m0 + wm + mt * 16 + tg + rp * 8;
            if (ml < Me) {
                int   tok = g_tok [e * T_TOK + ml];
                float mu  = g_mult[e * T_TOK + ml];
                float* dst = out + (size_t)tok * H_DIM + n0;
#pragma unroll
                for (int nt = 0; nt < 4; ++nt) {
                    int col = wn + nt * 8 + tt * 2;
                    atomicAdd(dst + col,           mu * accG[mt][nt][rp * 2]);
                    atomicAdd(dst + col + 1,       mu * accG[mt][nt][rp * 2 + 1]);
                    atomicAdd(dst + 128 + col,     mu * accU[mt][nt][rp * 2]);
                    atomicAdd(dst + 128 + col + 1, mu * accU[mt][nt][rp * 2 + 1]);
                }
            }
        }
}

// ---------------------------------------------------------------------------
// Launch
// ---------------------------------------------------------------------------
extern "C" void kernel_launch(void* const* d_in, const int* in_sizes, int n_in,
                              void* d_out, int out_size) {
    (void)in_sizes; (void)n_in; (void)out_size;
    const float* x   = (const float*)d_in[0];   // [T, H]
    const float* gw  = (const float*)d_in[1];   // [E, H]
    const float* ws  = (const float*)d_in[2];   // [E, 2I, H]
    const float* w2s = (const float*)d_in[3];   // [E, H, I]
    float* out = (float*)d_out;                 // [T, H]

    cudaFuncSetAttribute(k_ffn1, cudaFuncAttributeMaxDynamicSharedMemorySize, SMEMB);
    cudaFuncSetAttribute(k_ffn2, cudaFuncAttributeMaxDynamicSharedMemorySize, SMEMB);

    k_init<<<(T_TOK * H_DIM + 255) / 256, 256>>>(out);
    k_round_x<<<(T_TOK * H_DIM / 4 + 255) / 256, 256>>>(x);
    k_router<<<T_TOK, 256>>>(x, gw);
    k_ffn1<<<dim3(T_TOK / 128, I_DIM / 128, E_EXP), 256, SMEMB>>>(ws);
    k_ffn2<<<dim3(T_TOK / 128, (H_DIM / 256) * 2, E_EXP), 256, SMEMB>>>(w2s, out);
}

// round 9
// speedup vs baseline: 3.7940x; 1.0292x over previous
#include <cuda_runtime.h>
#include <math.h>
#include <stdint.h>

// Problem constants: T=1024 tokens, H=2048 hidden, I=4096 intermediate, E=8.
#define T_TOK 1024
#define H_DIM 2048
#define I_DIM 4096
#define E_EXP 8
#define TWO_I (2 * I_DIM)
#define JITTER2 0.02f   // 2 * JITTER_EPS

// GEMM tiling: CTA tile M=128 x N=256 (two 128-halves), BK=32 floats (=128B rows).
#define BKF     32
#define A_STG_B 16384                       // 128 rows * 128 B
#define B_STG_B 32768                       // 256 rows * 128 B
#define NSTG    3
#define SB_OFF  (NSTG * A_STG_B)            // 49152
#define SMEMB   (NSTG * (A_STG_B + B_STG_B) + 1024)   // 148480 (align pad)

// ---------------------------------------------------------------------------
// Device-global scratch (allocation-free rule)
// ---------------------------------------------------------------------------
__device__ int   g_cnt[E_EXP];
__device__ int   g_tok [E_EXP * T_TOK];
__device__ float g_mult[E_EXP * T_TOK];
__device__ __align__(128) float g_xr [(size_t)T_TOK * H_DIM];           // tf32-rounded x
__device__ __align__(128) float g_act[(size_t)E_EXP * T_TOK * I_DIM];   // silu(g)*u, rounded

// ---------------------------------------------------------------------------
// Helpers
// ---------------------------------------------------------------------------
__device__ __forceinline__ uint32_t f2tf32(float x) {
    uint32_t r;
    asm("cvt.rna.tf32.f32 %0, %1;" : "=r"(r) : "f"(x));
    return r;
}
__device__ __forceinline__ float rna(float x) { return __uint_as_float(f2tf32(x)); }

__device__ __forceinline__ void mma_tf32(float* c, const uint32_t* a, const uint32_t* b) {
    asm volatile(
        "mma.sync.aligned.m16n8k8.row.col.f32.tf32.tf32.f32 "
        "{%0,%1,%2,%3}, {%4,%5,%6,%7}, {%8,%9}, {%0,%1,%2,%3};"
        : "+f"(c[0]), "+f"(c[1]), "+f"(c[2]), "+f"(c[3])
        : "r"(a[0]), "r"(a[1]), "r"(a[2]), "r"(a[3]), "r"(b[0]), "r"(b[1]));
}

// ldmatrix x4 (b16) — used to load tf32 fragments (8x4-f32 == 8x8-b16 trick)
__device__ __forceinline__ void ldsm4(uint32_t* r, uint32_t addr) {
    asm volatile(
        "ldmatrix.sync.aligned.m8n8.x4.shared.b16 {%0,%1,%2,%3}, [%4];"
        : "=r"(r[0]), "=r"(r[1]), "=r"(r[2]), "=r"(r[3]) : "r"(addr));
}

__device__ __forceinline__ void cp16(uint32_t dst, const void* src) {
    asm volatile("cp.async.cg.shared.global [%0], [%1], 16;" :: "r"(dst), "l"(src) : "memory");
}
#define CP_COMMIT() asm volatile("cp.async.commit_group;" ::: "memory")
#define CP_WAIT(n)  asm volatile("cp.async.wait_group %0;" :: "n"(n) : "memory")

// ---------------------------------------------------------------------------
// Kernel 0: zero output + expert counters
// ---------------------------------------------------------------------------
__global__ void k_init(float* __restrict__ out) {
    int i = blockIdx.x * blockDim.x + threadIdx.x;
    if (i < E_EXP) g_cnt[i] = 0;
    if (i < T_TOK * H_DIM) out[i] = 0.0f;
}

// Pre-round x to tf32 (A-side of ffn1 needs no cvt in the mainloop)
__global__ void k_round_x(const float* __restrict__ x) {
    int i = blockIdx.x * blockDim.x + threadIdx.x;   // float4 index
    float4 v = ((const float4*)x)[i];
    v.x = rna(v.x); v.y = rna(v.y); v.z = rna(v.z); v.w = rna(v.w);
    ((float4*)g_xr)[i] = v;
}

// ---------------------------------------------------------------------------
// Kernel 1: router + sparsemixer + per-expert token lists (unchanged, passing)
// ---------------------------------------------------------------------------
__global__ void k_router(const float* __restrict__ x, const float* __restrict__ gw) {
    int t    = blockIdx.x;
    int warp = threadIdx.x >> 5;
    int lane = threadIdx.x & 31;

    const float4* xr = (const float4*)(x + (size_t)t * H_DIM);
    const float4* gr = (const float4*)(gw + (size_t)warp * H_DIM);

    float s = 0.0f;
    for (int i = lane; i < H_DIM / 4; i += 32) {
        float4 a = xr[i];
        float4 b = gr[i];
        s += a.x * b.x + a.y * b.y + a.z * b.z + a.w * b.w;
    }
#pragma unroll
    for (int o = 16; o > 0; o >>= 1) s += __shfl_xor_sync(0xFFFFFFFFu, s, o);

    __shared__ float sc[E_EXP];
    if (lane == 0) sc[warp] = s;
    __syncthreads();

    if (threadIdx.x == 0) {
        float sco[E_EXP];
#pragma unroll
        for (int e = 0; e < E_EXP; ++e) sco[e] = sc[e];

        float max1 = sco[0]; int ind1 = 0;
#pragma unroll
        for (int e = 1; e < E_EXP; ++e)
            if (sco[e] > max1) { max1 = sco[e]; ind1 = e; }
        float sum1 = 0.0f;
#pragma unroll
        for (int e = 0; e < E_EXP; ++e) {
            float factor = fmaxf(fabsf(sco[e]), max1);
            bool masked = (max1 - sco[e]) / factor > JITTER2;
            if (!masked) sum1 += expf(sco[e] - max1);
        }
        float mult1 = 1.0f / sum1;

        float max2 = -INFINITY; int ind2 = 0;
#pragma unroll
        for (int e = 0; e < E_EXP; ++e)
            if (e != ind1 && sco[e] > max2) { max2 = sco[e]; ind2 = e; }
        float sum2 = 0.0f;
#pragma unroll
        for (int e = 0; e < E_EXP; ++e) {
            if (e == ind1) continue;
            float factor = fmaxf(fabsf(sco[e]), max2);
            bool masked = (max2 - sco[e]) / factor > JITTER2;
            if (!masked) sum2 += expf(sco[e] - max2);
        }
        float mult2 = 1.0f / sum2;

        int p1 = atomicAdd(&g_cnt[ind1], 1);
        g_tok [ind1 * T_TOK + p1] = t;
        g_mult[ind1 * T_TOK + p1] = mult1;
        int p2 = atomicAdd(&g_cnt[ind2], 1);
        g_tok [ind2 * T_TOK + p2] = t;
        g_mult[ind2 * T_TOK + p2] = mult2;
    }
}

// ---------------------------------------------------------------------------
// Mainloop pieces. SW128-style XOR swizzle: float4-chunk c of row r lives at
// r*128 + ((c ^ (r&7))<<4). ldmatrix phases & cp.async are conflict-free.
// Requires in scope: smem_u32, smf, tid, pA[4],dA[4], pB[8],dB[8].
// ---------------------------------------------------------------------------
#define ISSUE_T(j)                                                              \
    do {                                                                        \
        int _s = (j) % NSTG; int _ko = (j) * BKF;                               \
        uint32_t _ab = smem_u32 + _s * A_STG_B;                                 \
        uint32_t _bb = smem_u32 + SB_OFF + _s * B_STG_B;                        \
        _Pragma("unroll") for (int q = 0; q < 4; ++q) cp16(_ab + dA[q], pA[q] + _ko); \
        _Pragma("unroll") for (int q = 0; q < 8; ++q) cp16(_bb + dB[q], pB[q] + _ko); \
        CP_COMMIT();                                                            \
    } while (0)

#define ROUND_B(j)                                                              \
    do {                                                                        \
        int _s = (j) % NSTG;                                                    \
        char* _bb = smf + SB_OFF + _s * B_STG_B;                                \
        _Pragma("unroll") for (int q = 0; q < 8; ++q) {                         \
            float4* _p = (float4*)(_bb + dB[q]);                                \
            float4 _v = *_p;                                                    \
            _v.x = rna(_v.x); _v.y = rna(_v.y);                                 \
            _v.z = rna(_v.z); _v.w = rna(_v.w);                                 \
            *_p = _v;                                                           \
        }                                                                       \
    } while (0)

// Fragment compute for one k32 stage. A rows 128, B halves G/U 128 rows each.
#define COMPUTE_STAGE(stg)                                                      \
    do {                                                                        \
        uint32_t aS = smem_u32 + (stg) * A_STG_B;                               \
        uint32_t gS = smem_u32 + SB_OFF + (stg) * B_STG_B;                      \
        uint32_t uS = gS + 128 * 128;                                           \
        _Pragma("unroll")                                                       \
        for (int ks = 0; ks < 4; ++ks) {                                        \
            uint32_t af[4][4], bgf[2][4], buf[2][4];                            \
            _Pragma("unroll")                                                   \
            for (int mt = 0; mt < 4; ++mt)                                      \
                ldsm4(af[mt], aS + rowOffA[mt] +                                \
                      ((uint32_t)((2 * ks + lhi) ^ swA[mt]) << 4));             \
            _Pragma("unroll")                                                   \
            for (int p = 0; p < 2; ++p) {                                       \
                uint32_t ch = (uint32_t)((2 * ks + q1) ^ swB[p]) << 4;          \
                ldsm4(bgf[p], gS + rowOffB[p] + ch);                            \
                ldsm4(buf[p], uS + rowOffB[p] + ch);                            \
            }                                                                   \
            _Pragma("unroll")                                                   \
            for (int mt = 0; mt < 4; ++mt)                                      \
                _Pragma("unroll")                                               \
                for (int p = 0; p < 2; ++p) {                                   \
                    mma_tf32(accG[mt][2 * p],     af[mt], &bgf[p][0]);          \
                    mma_tf32(accG[mt][2 * p + 1], af[mt], &bgf[p][2]);          \
                    mma_tf32(accU[mt][2 * p],     af[mt], &buf[p][0]);          \
                    mma_tf32(accU[mt][2 * p + 1], af[mt], &buf[p][2]);          \
                }                                                               \
        }                                                                       \
    } while (0)

// Pipelined mainloop, ONE barrier per iteration.
// At iter t: stage t%3 = compute, (t+1)%3 = round (landed), (t+2)%3 = in flight.
// ISSUE_T(t+2) reuses stage (t-1)%3, freed by compute(t-1) which the top
// barrier ordered. CP_WAIT(1) with groups {t+1,t+2} in flight => t+1 landed.
// Each thread rounds exactly the chunks it cp.async'd (same dB[]), so
// wait_group gives thread-local visibility; the next top barrier publishes
// the rounded STS to all warps before their LDSM.
#define GEMM_MAINLOOP(NT)                                                       \
    ISSUE_T(0); ISSUE_T(1);                                                     \
    CP_WAIT(1);                                                                 \
    ROUND_B(0);                                                                 \
    for (int t = 0; t < (NT); ++t) {                                            \
        __syncthreads();                                                        \
        if (t + 2 < (NT))      { ISSUE_T(t + 2); CP_WAIT(1); ROUND_B(t + 1); }  \
        else if (t + 1 < (NT)) { CP_WAIT(0); ROUND_B(t + 1); }                  \
        COMPUTE_STAGE(t % NSTG);                                                \
    }

// Per-warp/lane fragment index setup (shared by both GEMMs)
#define FRAG_SETUP()                                                            \
    int warp = tid >> 5, lane = tid & 31;                                       \
    int wm = (warp & 1) * 64, wn = (warp >> 1) * 32;                            \
    int tg = lane >> 2, tt = lane & 3;                                          \
    int l16 = lane & 15, lhi = lane >> 4, q1 = (lane >> 3) & 1;                 \
    uint32_t rowOffA[4], swA[4], rowOffB[2], swB[2];                            \
    _Pragma("unroll")                                                           \
    for (int mt = 0; mt < 4; ++mt) {                                            \
        int r = wm + mt * 16 + l16;                                             \
        rowOffA[mt] = (uint32_t)r * 128; swA[mt] = (uint32_t)(r & 7);           \
    }                                                                           \
    _Pragma("unroll")                                                           \
    for (int p = 0; p < 2; ++p) {                                               \
        int r = wn + p * 16 + ((lane >> 4) << 3) + (lane & 7);                  \
        rowOffB[p] = (uint32_t)r * 128; swB[p] = (uint32_t)(r & 7);             \
    }                                                                           \
    float accG[4][4][4], accU[4][4][4];                                         \
    _Pragma("unroll")                                                           \
    for (int i = 0; i < 4; ++i)                                                 \
        _Pragma("unroll")                                                       \
        for (int j = 0; j < 4; ++j)                                             \
            _Pragma("unroll")                                                   \
            for (int r = 0; r < 4; ++r) { accG[i][j][r] = 0.f; accU[i][j][r] = 0.f; }

// ---------------------------------------------------------------------------
// GEMM 1 + fused SiLU: act[e,m,n] = rna(silu(x@wg^T) * (x@wu^T))
// CTA: 128 tokens x (128 gate cols n0.. + 128 up cols I+n0..). K = H = 2048.
// ---------------------------------------------------------------------------
__global__ __launch_bounds__(256, 1)
void k_ffn1(const float* __restrict__ ws) {
    int e  = blockIdx.z;
    int Me = g_cnt[e];
    int m0 = blockIdx.x * 128;
    if (m0 >= Me) return;
    int n0 = blockIdx.y * 128;

    extern __shared__ float sm_raw[];
    uint32_t raw_u32  = (uint32_t)__cvta_generic_to_shared(sm_raw);
    uint32_t smem_u32 = (raw_u32 + 1023) & ~1023u;
    char* smf = (char*)sm_raw + (smem_u32 - raw_u32);
    __shared__ int stok[128];

    int tid = threadIdx.x;
    if (tid < 128) {
        int m = m0 + tid;
        stok[tid] = (m < Me) ? g_tok[e * T_TOK + m] : g_tok[e * T_TOK];
    }
    __syncthreads();

    // cp.async assignments: A 4 chunks/thread, B 8 chunks/thread
    const float* pA[4]; uint32_t dA[4];
#pragma unroll
    for (int q = 0; q < 4; ++q) {
        int a = q * 256 + tid, r = a >> 3, c = a & 7;
        pA[q] = g_xr + (size_t)stok[r] * H_DIM + c * 4;
        dA[q] = r * 128 + ((c ^ (r & 7)) << 4);
    }
    const float* pB[8]; uint32_t dB[8];
    const float* wbase = ws + (size_t)e * TWO_I * H_DIM;
#pragma unroll
    for (int q = 0; q < 8; ++q) {
        int b = q * 256 + tid, r = b >> 3, c = b & 7;
        int rowg = (r < 128) ? (n0 + r) : (I_DIM + n0 + (r - 128));
        pB[q] = wbase + (size_t)rowg * H_DIM + c * 4;
        dB[q] = r * 128 + ((c ^ (r & 7)) << 4);
    }

    FRAG_SETUP();
    GEMM_MAINLOOP(H_DIM / BKF);

    // epilogue: act = rna(silu(g) * u), float2 stores
    float* actb = g_act + (size_t)e * T_TOK * I_DIM + n0;
#pragma unroll
    for (int mt = 0; mt < 4; ++mt)
#pragma unroll
        for (int rp = 0; rp < 2; ++rp) {
            int m = m0 + wm + mt * 16 + tg + rp * 8;
            if (m < Me) {
                float* arow = actb + (size_t)m * I_DIM;
#pragma unroll
                for (int nt = 0; nt < 4; ++nt) {
                    int col = wn + nt * 8 + tt * 2;
                    float g0 = accG[mt][nt][rp * 2], g1 = accG[mt][nt][rp * 2 + 1];
                    float u0 = accU[mt][nt][rp * 2], u1 = accU[mt][nt][rp * 2 + 1];
                    float2 v;
                    v.x = rna(g0 / (1.0f + expf(-g0)) * u0);
                    v.y = rna(g1 / (1.0f + expf(-g1)) * u1);
                    *(float2*)(arow + col) = v;
                }
            }
        }
}

// ---------------------------------------------------------------------------
// GEMM 2 + scatter: out[tok,n] += mult * (act @ w2s^T)
// CTA: 128 rows x 256 out cols, K-split x2 (blockIdx.y bit0).
// ---------------------------------------------------------------------------
__global__ __launch_bounds__(256, 1)
void k_ffn2(const float* __restrict__ w2s, float* __restrict__ out) {
    int e  = blockIdx.z;
    int Me = g_cnt[e];
    int m0 = blockIdx.x * 128;
    if (m0 >= Me) return;
    int n0  = (blockIdx.y >> 1) * 256;
    int kb0 = (blockIdx.y & 1) * (I_DIM / 2);

    extern __shared__ float sm_raw[];
    uint32_t raw_u32  = (uint32_t)__cvta_generic_to_shared(sm_raw);
    uint32_t smem_u32 = (raw_u32 + 1023) & ~1023u;
    char* smf = (char*)sm_raw + (smem_u32 - raw_u32);

    int tid = threadIdx.x;

    const float* pA[4]; uint32_t dA[4];
    const float* abase = g_act + ((size_t)e * T_TOK + m0) * I_DIM + kb0;
#pragma unroll
    for (int q = 0; q < 4; ++q) {
        int a = q * 256 + tid, r = a >> 3, c = a & 7;
        pA[q] = abase + (size_t)r * I_DIM + c * 4;
        dA[q] = r * 128 + ((c ^ (r & 7)) << 4);
    }
    const float* pB[8]; uint32_t dB[8];
    const float* wbase = w2s + (size_t)e * H_DIM * I_DIM + kb0;
#pragma unroll
    for (int q = 0; q < 8; ++q) {
        int b = q * 256 + tid, r = b >> 3, c = b & 7;
        pB[q] = wbase + (size_t)(n0 + r) * I_DIM + c * 4;
        dB[q] = r * 128 + ((c ^ (r & 7)) << 4);
    }

    FRAG_SETUP();
    GEMM_MAINLOOP((I_DIM / 2) / BKF);

    // scatter epilogue: out[tok, n] += mult * v  (commutative adds)
#pragma unroll
    for (int mt = 0; mt < 4; ++mt)
#pragma unroll
        for (int rp = 0; rp < 2; ++rp) {
            int ml = m0 + wm + mt * 16 + tg + rp * 8;
            if (ml < Me) {
                int   tok = g_tok [e * T_TOK + ml];
                float mu  = g_mult[e * T_TOK + ml];
                float* dst = out + (size_t)tok * H_DIM + n0;
#pragma unroll
                for (int nt = 0; nt < 4; ++nt) {
                    int col = wn + nt * 8 + tt * 2;
                    atomicAdd(dst + col,           mu * accG[mt][nt][rp * 2]);
                    atomicAdd(dst + col + 1,       mu * accG[mt][nt][rp * 2 + 1]);
                    atomicAdd(dst + 128 + col,     mu * accU[mt][nt][rp * 2]);
                    atomicAdd(dst + 128 + col + 1, mu * accU[mt][nt][rp * 2 + 1]);
                }
            }
        }
}

// ---------------------------------------------------------------------------
// Launch
// ---------------------------------------------------------------------------
extern "C" void kernel_launch(void* const* d_in, const int* in_sizes, int n_in,
                              void* d_out, int out_size) {
    (void)in_sizes; (void)n_in; (void)out_size;
    const float* x   = (const float*)d_in[0];   // [T, H]
    const float* gw  = (const float*)d_in[1];   // [E, H]
    const float* ws  = (const float*)d_in[2];   // [E, 2I, H]
    const float* w2s = (const float*)d_in[3];   // [E, H, I]
    float* out = (float*)d_out;                 // [T, H]

    cudaFuncSetAttribute(k_ffn1, cudaFuncAttributeMaxDynamicSharedMemorySize, SMEMB);
    cudaFuncSetAttribute(k_ffn2, cudaFuncAttributeMaxDynamicSharedMemorySize, SMEMB);

    k_init<<<(T_TOK * H_DIM + 255) / 256, 256>>>(out);
    k_round_x<<<(T_TOK * H_DIM / 4 + 255) / 256, 256>>>(x);
    k_router<<<T_TOK, 256>>>(x, gw);
    k_ffn1<<<dim3(T_TOK / 128, I_DIM / 128, E_EXP), 256, SMEMB>>>(ws);
    k_ffn2<<<dim3(T_TOK / 128, (H_DIM / 256) * 2, E_EXP), 256, SMEMB>>>(w2s, out);
}

// round 11
// speedup vs baseline: 3.8450x; 1.0134x over previous
#include <cuda_runtime.h>
#include <math.h>
#include <stdint.h>

// Problem constants: T=1024 tokens, H=2048 hidden, I=4096 intermediate, E=8.
#define T_TOK 1024
#define H_DIM 2048
#define I_DIM 4096
#define E_EXP 8
#define TWO_I (2 * I_DIM)
#define JITTER2 0.02f   // 2 * JITTER_EPS

// GEMM tiling: CTA tile M=128 x N=256 (two 128-halves), BK=32 floats (=128B rows).
// 512 threads / 16 warps: warp tile 64(m) x 16(n) per G/U half.
#define BKF     32
#define A_STG_B 16384                       // 128 rows * 128 B
#define B_STG_B 32768                       // 256 rows * 128 B
#define NSTG    3
#define SB_OFF  (NSTG * A_STG_B)            // 49152
#define SMEMB   (NSTG * (A_STG_B + B_STG_B) + 1024)   // 148480 (align pad)

// ---------------------------------------------------------------------------
// Device-global scratch (allocation-free rule)
// ---------------------------------------------------------------------------
__device__ int   g_cnt[E_EXP];
__device__ int   g_tok [E_EXP * T_TOK];
__device__ float g_mult[E_EXP * T_TOK];
__device__ __align__(128) float g_xr [(size_t)T_TOK * H_DIM];           // tf32-rounded x
__device__ __align__(128) float g_act[(size_t)E_EXP * T_TOK * I_DIM];   // silu(g)*u, rounded

// ---------------------------------------------------------------------------
// Helpers
// ---------------------------------------------------------------------------
__device__ __forceinline__ uint32_t f2tf32(float x) {
    uint32_t r;
    asm("cvt.rna.tf32.f32 %0, %1;" : "=r"(r) : "f"(x));
    return r;
}
__device__ __forceinline__ float rna(float x) { return __uint_as_float(f2tf32(x)); }

__device__ __forceinline__ void mma_tf32(float* c, const uint32_t* a, const uint32_t* b) {
    asm volatile(
        "mma.sync.aligned.m16n8k8.row.col.f32.tf32.tf32.f32 "
        "{%0,%1,%2,%3}, {%4,%5,%6,%7}, {%8,%9}, {%0,%1,%2,%3};"
        : "+f"(c[0]), "+f"(c[1]), "+f"(c[2]), "+f"(c[3])
        : "r"(a[0]), "r"(a[1]), "r"(a[2]), "r"(a[3]), "r"(b[0]), "r"(b[1]));
}

// ldmatrix x4 (b16) — used to load tf32 fragments (8x4-f32 == 8x8-b16 trick)
__device__ __forceinline__ void ldsm4(uint32_t* r, uint32_t addr) {
    asm volatile(
        "ldmatrix.sync.aligned.m8n8.x4.shared.b16 {%0,%1,%2,%3}, [%4];"
        : "=r"(r[0]), "=r"(r[1]), "=r"(r[2]), "=r"(r[3]) : "r"(addr));
}

__device__ __forceinline__ void cp16(uint32_t dst, const void* src) {
    asm volatile("cp.async.cg.shared.global [%0], [%1], 16;" :: "r"(dst), "l"(src) : "memory");
}
#define CP_COMMIT() asm volatile("cp.async.commit_group;" ::: "memory")
#define CP_WAIT(n)  asm volatile("cp.async.wait_group %0;" :: "n"(n) : "memory")

// ---------------------------------------------------------------------------
// Kernel 0: zero output + expert counters
// ---------------------------------------------------------------------------
__global__ void k_init(float* __restrict__ out) {
    int i = blockIdx.x * blockDim.x + threadIdx.x;
    if (i < E_EXP) g_cnt[i] = 0;
    if (i < T_TOK * H_DIM) out[i] = 0.0f;
}

// Pre-round x to tf32 (A-side of ffn1 needs no cvt in the mainloop)
__global__ void k_round_x(const float* __restrict__ x) {
    int i = blockIdx.x * blockDim.x + threadIdx.x;   // float4 index
    float4 v = ((const float4*)x)[i];
    v.x = rna(v.x); v.y = rna(v.y); v.z = rna(v.z); v.w = rna(v.w);
    ((float4*)g_xr)[i] = v;
}

// ---------------------------------------------------------------------------
// Kernel 1: router + sparsemixer + per-expert token lists (unchanged, passing)
// ---------------------------------------------------------------------------
__global__ void k_router(const float* __restrict__ x, const float* __restrict__ gw) {
    int t    = blockIdx.x;
    int warp = threadIdx.x >> 5;
    int lane = threadIdx.x & 31;

    const float4* xr = (const float4*)(x + (size_t)t * H_DIM);
    const float4* gr = (const float4*)(gw + (size_t)warp * H_DIM);

    float s = 0.0f;
    for (int i = lane; i < H_DIM / 4; i += 32) {
        float4 a = xr[i];
        float4 b = gr[i];
        s += a.x * b.x + a.y * b.y + a.z * b.z + a.w * b.w;
    }
#pragma unroll
    for (int o = 16; o > 0; o >>= 1) s += __shfl_xor_sync(0xFFFFFFFFu, s, o);

    __shared__ float sc[E_EXP];
    if (lane == 0) sc[warp] = s;
    __syncthreads();

    if (threadIdx.x == 0) {
        float sco[E_EXP];
#pragma unroll
        for (int e = 0; e < E_EXP; ++e) sco[e] = sc[e];

        float max1 = sco[0]; int ind1 = 0;
#pragma unroll
        for (int e = 1; e < E_EXP; ++e)
            if (sco[e] > max1) { max1 = sco[e]; ind1 = e; }
        float sum1 = 0.0f;
#pragma unroll
        for (int e = 0; e < E_EXP; ++e) {
            float factor = fmaxf(fabsf(sco[e]), max1);
            bool masked = (max1 - sco[e]) / factor > JITTER2;
            if (!masked) sum1 += expf(sco[e] - max1);
        }
        float mult1 = 1.0f / sum1;

        float max2 = -INFINITY; int ind2 = 0;
#pragma unroll
        for (int e = 0; e < E_EXP; ++e)
            if (e != ind1 && sco[e] > max2) { max2 = sco[e]; ind2 = e; }
        float sum2 = 0.0f;
#pragma unroll
        for (int e = 0; e < E_EXP; ++e) {
            if (e == ind1) continue;
            float factor = fmaxf(fabsf(sco[e]), max2);
            bool masked = (max2 - sco[e]) / factor > JITTER2;
            if (!masked) sum2 += expf(sco[e] - max2);
        }
        float mult2 = 1.0f / sum2;

        int p1 = atomicAdd(&g_cnt[ind1], 1);
        g_tok [ind1 * T_TOK + p1] = t;
        g_mult[ind1 * T_TOK + p1] = mult1;
        int p2 = atomicAdd(&g_cnt[ind2], 1);
        g_tok [ind2 * T_TOK + p2] = t;
        g_mult[ind2 * T_TOK + p2] = mult2;
    }
}

// ---------------------------------------------------------------------------
// Mainloop pieces. SW128-style XOR swizzle: float4-chunk c of row r lives at
// r*128 + ((c ^ (r&7))<<4). ldmatrix phases & cp.async are conflict-free.
// 512 threads: A = 2 chunks/thread, B = 4 chunks/thread.
// Requires in scope: smem_u32, smf, tid, pA[2],dA[2], pB[4],dB[4].
// ---------------------------------------------------------------------------
#define ISSUE_T(j)                                                              \
    do {                                                                        \
        int _s = (j) % NSTG; int _ko = (j) * BKF;                               \
        uint32_t _ab = smem_u32 + _s * A_STG_B;                                 \
        uint32_t _bb = smem_u32 + SB_OFF + _s * B_STG_B;                        \
        _Pragma("unroll") for (int q = 0; q < 2; ++q) cp16(_ab + dA[q], pA[q] + _ko); \
        _Pragma("unroll") for (int q = 0; q < 4; ++q) cp16(_bb + dB[q], pB[q] + _ko); \
        CP_COMMIT();                                                            \
    } while (0)

#define ROUND_B(j)                                                              \
    do {                                                                        \
        int _s = (j) % NSTG;                                                    \
        char* _bb = smf + SB_OFF + _s * B_STG_B;                                \
        _Pragma("unroll") for (int q = 0; q < 4; ++q) {                         \
            float4* _p = (float4*)(_bb + dB[q]);                                \
            float4 _v = *_p;                                                    \
            _v.x = rna(_v.x); _v.y = rna(_v.y);                                 \
            _v.z = rna(_v.z); _v.w = rna(_v.w);                                 \
            *_p = _v;                                                           \
        }                                                                       \
    } while (0)

// Fragment compute for one k32 stage. Warp tile 64(m) x 16(n) per G/U half.
#define COMPUTE_STAGE(stg)                                                      \
    do {                                                                        \
        uint32_t aS = smem_u32 + (stg) * A_STG_B;                               \
        uint32_t gS = smem_u32 + SB_OFF + (stg) * B_STG_B;                      \
        uint32_t uS = gS + 128 * 128;                                           \
        _Pragma("unroll")                                                       \
        for (int ks = 0; ks < 4; ++ks) {                                        \
            uint32_t af[4][4], bgf[4], buf[4];                                  \
            _Pragma("unroll")                                                   \
            for (int mt = 0; mt < 4; ++mt)                                      \
                ldsm4(af[mt], aS + rowOffA[mt] +                                \
                      ((uint32_t)((2 * ks + lhi) ^ swA[mt]) << 4));             \
            {                                                                   \
                uint32_t ch = (uint32_t)((2 * ks + q1) ^ swB) << 4;             \
                ldsm4(bgf, gS + rowOffB + ch);                                  \
                ldsm4(buf, uS + rowOffB + ch);                                  \
            }                                                                   \
            _Pragma("unroll")                                                   \
            for (int mt = 0; mt < 4; ++mt) {                                    \
                mma_tf32(accG[mt][0], af[mt], &bgf[0]);                         \
                mma_tf32(accG[mt][1], af[mt], &bgf[2]);                         \
                mma_tf32(accU[mt][0], af[mt], &buf[0]);                         \
                mma_tf32(accU[mt][1], af[mt], &buf[2]);                         \
            }                                                                   \
        }                                                                       \
    } while (0)

// Pipelined mainloop, ONE barrier per iteration (see R9 comment for hazards).
#define GEMM_MAINLOOP(NT)                                                       \
    ISSUE_T(0); ISSUE_T(1);                                                     \
    CP_WAIT(1);                                                                 \
    ROUND_B(0);                                                                 \
    for (int t = 0; t < (NT); ++t) {                                            \
        __syncthreads();                                                        \
        if (t + 2 < (NT))      { ISSUE_T(t + 2); CP_WAIT(1); ROUND_B(t + 1); }  \
        else if (t + 1 < (NT)) { CP_WAIT(0); ROUND_B(t + 1); }                  \
        COMPUTE_STAGE(t % NSTG);                                                \
    }

// Per-warp/lane fragment index setup. 16 warps: 2(m) x 8(n).
#define FRAG_SETUP()                                                            \
    int warp = tid >> 5, lane = tid & 31;                                       \
    int wm = (warp & 1) * 64, wn = (warp >> 1) * 16;                            \
    int tg = lane >> 2, tt = lane & 3;                                          \
    int l16 = lane & 15, lhi = lane >> 4, q1 = (lane >> 3) & 1;                 \
    uint32_t rowOffA[4], swA[4];                                                \
    _Pragma("unroll")                                                           \
    for (int mt = 0; mt < 4; ++mt) {                                            \
        int r = wm + mt * 16 + l16;                                             \
        rowOffA[mt] = (uint32_t)r * 128; swA[mt] = (uint32_t)(r & 7);           \
    }                                                                           \
    uint32_t rowOffB, swB;                                                      \
    {                                                                           \
        int r = wn + ((lane >> 4) << 3) + (lane & 7);                           \
        rowOffB = (uint32_t)r * 128; swB = (uint32_t)(r & 7);                   \
    }                                                                           \
    float accG[4][2][4], accU[4][2][4];                                         \
    _Pragma("unroll")                                                           \
    for (int i = 0; i < 4; ++i)                                                 \
        _Pragma("unroll")                                                       \
        for (int j = 0; j < 2; ++j)                                             \
            _Pragma("unroll")                                                   \
            for (int r = 0; r < 4; ++r) { accG[i][j][r] = 0.f; accU[i][j][r] = 0.f; }

// ---------------------------------------------------------------------------
// GEMM 1 + fused SiLU: act[e,m,n] = rna(silu(x@wg^T) * (x@wu^T))
// CTA: 128 tokens x (128 gate cols n0.. + 128 up cols I+n0..). K = H = 2048.
// ---------------------------------------------------------------------------
__global__ __launch_bounds__(512, 1)
void k_ffn1(const float* __restrict__ ws) {
    int e  = blockIdx.z;
    int Me = g_cnt[e];
    int m0 = blockIdx.x * 128;
    if (m0 >= Me) return;
    int n0 = blockIdx.y * 128;

    extern __shared__ float sm_raw[];
    uint32_t raw_u32  = (uint32_t)__cvta_generic_to_shared(sm_raw);
    uint32_t smem_u32 = (raw_u32 + 1023) & ~1023u;
    char* smf = (char*)sm_raw + (smem_u32 - raw_u32);
    __shared__ int stok[128];

    int tid = threadIdx.x;
    if (tid < 128) {
        int m = m0 + tid;
        stok[tid] = (m < Me) ? g_tok[e * T_TOK + m] : g_tok[e * T_TOK];
    }
    __syncthreads();

    // cp.async assignments: A 2 chunks/thread, B 4 chunks/thread
    const float* pA[2]; uint32_t dA[2];
#pragma unroll
    for (int q = 0; q < 2; ++q) {
        int a = q * 512 + tid, r = a >> 3, c = a & 7;
        pA[q] = g_xr + (size_t)stok[r] * H_DIM + c * 4;
        dA[q] = r * 128 + ((c ^ (r & 7)) << 4);
    }
    const float* pB[4]; uint32_t dB[4];
    const float* wbase = ws + (size_t)e * TWO_I * H_DIM;
#pragma unroll
    for (int q = 0; q < 4; ++q) {
        int b = q * 512 + tid, r = b >> 3, c = b & 7;
        int rowg = (r < 128) ? (n0 + r) : (I_DIM + n0 + (r - 128));
        pB[q] = wbase + (size_t)rowg * H_DIM + c * 4;
        dB[q] = r * 128 + ((c ^ (r & 7)) << 4);
    }

    FRAG_SETUP();
    GEMM_MAINLOOP(H_DIM / BKF);

    // epilogue: act = rna(silu(g) * u), float2 stores
    float* actb = g_act + (size_t)e * T_TOK * I_DIM + n0;
#pragma unroll
    for (int mt = 0; mt < 4; ++mt)
#pragma unroll
        for (int rp = 0; rp < 2; ++rp) {
            int m = m0 + wm + mt * 16 + tg + rp * 8;
            if (m < Me) {
                float* arow = actb + (size_t)m * I_DIM;
#pragma unroll
                for (int nt = 0; nt < 2; ++nt) {
                    int col = wn + nt * 8 + tt * 2;
                    float g0 = accG[mt][nt][rp * 2], g1 = accG[mt][nt][rp * 2 + 1];
                    float u0 = accU[mt][nt][rp * 2], u1 = accU[mt][nt][rp * 2 + 1];
                    float2 v;
                    v.x = rna(g0 / (1.0f + expf(-g0)) * u0);
                    v.y = rna(g1 / (1.0f + expf(-g1)) * u1);
                    *(float2*)(arow + col) = v;
                }
            }
        }
}

// ---------------------------------------------------------------------------
// GEMM 2 + scatter: out[tok,n] += mult * (act @ w2s^T)
// CTA: 128 rows x 256 out cols, K-split x2 (blockIdx.y bit0).
// ---------------------------------------------------------------------------
__global__ __launch_bounds__(512, 1)
void k_ffn2(const float* __restrict__ w2s, float* __restrict__ out) {
    int e  = blockIdx.z;
    int Me = g_cnt[e];
    int m0 = blockIdx.x * 128;
    if (m0 >= Me) return;
    int n0  = (blockIdx.y >> 1) * 256;
    int kb0 = (blockIdx.y & 1) * (I_DIM / 2);

    extern __shared__ float sm_raw[];
    uint32_t raw_u32  = (uint32_t)__cvta_generic_to_shared(sm_raw);
    uint32_t smem_u32 = (raw_u32 + 1023) & ~1023u;
    char* smf = (char*)sm_raw + (smem_u32 - raw_u32);

    int tid = threadIdx.x;

    const float* pA[2]; uint32_t dA[2];
    const float* abase = g_act + ((size_t)e * T_TOK + m0) * I_DIM + kb0;
#pragma unroll
    for (int q = 0; q < 2; ++q) {
        int a = q * 512 + tid, r = a >> 3, c = a & 7;
        pA[q] = abase + (size_t)r * I_DIM + c * 4;
        dA[q] = r * 128 + ((c ^ (r & 7)) << 4);
    }
    const float* pB[4]; uint32_t dB[4];
    const float* wbase = w2s + (size_t)e * H_DIM * I_DIM + kb0;
#pragma unroll
    for (int q = 0; q < 4; ++q) {
        int b = q * 512 + tid, r = b >> 3, c = b & 7;
        pB[q] = wbase + (size_t)(n0 + r) * I_DIM + c * 4;
        dB[q] = r * 128 + ((c ^ (r & 7)) << 4);
    }

    FRAG_SETUP();
    GEMM_MAINLOOP((I_DIM / 2) / BKF);

    // scatter epilogue: out[tok, n] += mult * v  (commutative adds)
#pragma unroll
    for (int mt = 0; mt < 4; ++mt)
#pragma unroll
        for (int rp = 0; rp < 2; ++rp) {
            int ml = m0 + wm + mt * 16 + tg + rp * 8;
            if (ml < Me) {
                int   tok = g_tok [e * T_TOK + ml];
                float mu  = g_mult[e * T_TOK + ml];
                float* dst = out + (size_t)tok * H_DIM + n0;
#pragma unroll
                for (int nt = 0; nt < 2; ++nt) {
                    int col = wn + nt * 8 + tt * 2;
                    atomicAdd(dst + col,           mu * accG[mt][nt][rp * 2]);
                    atomicAdd(dst + col + 1,       mu * accG[mt][nt][rp * 2 + 1]);
                    atomicAdd(dst + 128 + col,     mu * accU[mt][nt][rp * 2]);
                    atomicAdd(dst + 128 + col + 1, mu * accU[mt][nt][rp * 2 + 1]);
                }
            }
        }
}

// ---------------------------------------------------------------------------
// Launch
// ---------------------------------------------------------------------------
extern "C" void kernel_launch(void* const* d_in, const int* in_sizes, int n_in,
                              void* d_out, int out_size) {
    (void)in_sizes; (void)n_in; (void)out_size;
    const float* x   = (const float*)d_in[0];   // [T, H]
    const float* gw  = (const float*)d_in[1];   // [E, H]
    const float* ws  = (const float*)d_in[2];   // [E, 2I, H]
    const float* w2s = (const float*)d_in[3];   // [E, H, I]
    float* out = (float*)d_out;                 // [T, H]

    cudaFuncSetAttribute(k_ffn1, cudaFuncAttributeMaxDynamicSharedMemorySize, SMEMB);
    cudaFuncSetAttribute(k_ffn2, cudaFuncAttributeMaxDynamicSharedMemorySize, SMEMB);

    k_init<<<(T_TOK * H_DIM + 255) / 256, 256>>>(out);
    k_round_x<<<(T_TOK * H_DIM / 4 + 255) / 256, 256>>>(x);
    k_router<<<T_TOK, 256>>>(x, gw);
    k_ffn1<<<dim3(T_TOK / 128, I_DIM / 128, E_EXP), 512, SMEMB>>>(ws);
    k_ffn2<<<dim3(T_TOK / 128, (H_DIM / 256) * 2, E_EXP), 512, SMEMB>>>(w2s, out);
}

// round 15
// speedup vs baseline: 6.2923x; 1.6365x over previous
#include <cuda_runtime.h>
#include <cuda_fp16.h>
#include <math.h>
#include <stdint.h>

// Problem constants: T=1024 tokens, H=2048 hidden, I=4096 intermediate, E=8.
#define T_TOK 1024
#define H_DIM 2048
#define I_DIM 4096
#define E_EXP 8
#define TWO_I (2 * I_DIM)
#define JITTER2 0.02f   // 2 * JITTER_EPS

// GEMM tiling: CTA tile M=128 x N=256 (two 128-halves), BK=32 (k16 x2 per tile).
// 512 threads / 16 warps as 2(m) x 8(n); warp tile 64(m) x 16(n) per G/U half.
// A in smem: fp16, 128 rows x 64B. B: fp32 staged (128B rows) + fp16 tile (64B rows).
#define BKF     32
#define AH_STG  8192                         // 128 * 64
#define BF_STG  32768                        // 256 * 128
#define BH_STG  16384                        // 256 * 64
#define NSTG    3
#define BF_OFF  (NSTG * AH_STG)              // 24576
#define BH_OFF  (BF_OFF + NSTG * BF_STG)     // 122880
#define SMEMB   (BH_OFF + NSTG * BH_STG + 1024)  // 173056

// ---------------------------------------------------------------------------
// Device-global scratch (allocation-free rule)
// ---------------------------------------------------------------------------
__device__ int   g_cnt[E_EXP];
__device__ int   g_tok [E_EXP * T_TOK];
__device__ float g_mult[E_EXP * T_TOK];
__device__ __align__(128) __half g_xh [(size_t)T_TOK * H_DIM];           // fp16 x
__device__ __align__(128) __half g_acth[(size_t)E_EXP * T_TOK * I_DIM];  // fp16 act

// ---------------------------------------------------------------------------
// Helpers
// ---------------------------------------------------------------------------
__device__ __forceinline__ uint32_t pack_f16x2(float lo, float hi) {
    uint32_t r;  // PTX: cvt d, a, b -> hi=cvt(a), lo=cvt(b)
    asm("cvt.rn.f16x2.f32 %0, %1, %2;" : "=r"(r) : "f"(hi), "f"(lo));
    return r;
}

__device__ __forceinline__ void mma_f16(float* c, const uint32_t* a, const uint32_t* b) {
    asm volatile(
        "mma.sync.aligned.m16n8k16.row.col.f32.f16.f16.f32 "
        "{%0,%1,%2,%3}, {%4,%5,%6,%7}, {%8,%9}, {%0,%1,%2,%3};"
        : "+f"(c[0]), "+f"(c[1]), "+f"(c[2]), "+f"(c[3])
        : "r"(a[0]), "r"(a[1]), "r"(a[2]), "r"(a[3]), "r"(b[0]), "r"(b[1]));
}

__device__ __forceinline__ void ldsm4(uint32_t* r, uint32_t addr) {
    asm volatile(
        "ldmatrix.sync.aligned.m8n8.x4.shared.b16 {%0,%1,%2,%3}, [%4];"
        : "=r"(r[0]), "=r"(r[1]), "=r"(r[2]), "=r"(r[3]) : "r"(addr));
}

__device__ __forceinline__ void cp16(uint32_t dst, const void* src) {
    asm volatile("cp.async.cg.shared.global [%0], [%1], 16;" :: "r"(dst), "l"(src) : "memory");
}
#define CP_COMMIT() asm volatile("cp.async.commit_group;" ::: "memory")
#define CP_WAIT(n)  asm volatile("cp.async.wait_group %0;" :: "n"(n) : "memory")

// ---------------------------------------------------------------------------
// Kernel 0: zero output + expert counters
// ---------------------------------------------------------------------------
__global__ void k_init(float* __restrict__ out) {
    int i = blockIdx.x * blockDim.x + threadIdx.x;
    if (i < E_EXP) g_cnt[i] = 0;
    if (i < T_TOK * H_DIM) out[i] = 0.0f;
}

// Convert x to fp16 once (A-side of ffn1)
__global__ void k_cvt_x(const float* __restrict__ x) {
    int i = blockIdx.x * blockDim.x + threadIdx.x;   // float4 index
    float4 v = ((const float4*)x)[i];
    uint2 h;
    h.x = pack_f16x2(v.x, v.y);
    h.y = pack_f16x2(v.z, v.w);
    ((uint2*)g_xh)[i] = h;
}

// ---------------------------------------------------------------------------
// Kernel 1: router + sparsemixer + per-expert token lists (unchanged, passing)
// ---------------------------------------------------------------------------
__global__ void k_router(const float* __restrict__ x, const float* __restrict__ gw) {
    int t    = blockIdx.x;
    int warp = threadIdx.x >> 5;
    int lane = threadIdx.x & 31;

    const float4* xr = (const float4*)(x + (size_t)t * H_DIM);
    const float4* gr = (const float4*)(gw + (size_t)warp * H_DIM);

    float s = 0.0f;
    for (int i = lane; i < H_DIM / 4; i += 32) {
        float4 a = xr[i];
        float4 b = gr[i];
        s += a.x * b.x + a.y * b.y + a.z * b.z + a.w * b.w;
    }
#pragma unroll
    for (int o = 16; o > 0; o >>= 1) s += __shfl_xor_sync(0xFFFFFFFFu, s, o);

    __shared__ float sc[E_EXP];
    if (lane == 0) sc[warp] = s;
    __syncthreads();

    if (threadIdx.x == 0) {
        float sco[E_EXP];
#pragma unroll
        for (int e = 0; e < E_EXP; ++e) sco[e] = sc[e];

        float max1 = sco[0]; int ind1 = 0;
#pragma unroll
        for (int e = 1; e < E_EXP; ++e)
            if (sco[e] > max1) { max1 = sco[e]; ind1 = e; }
        float sum1 = 0.0f;
#pragma unroll
        for (int e = 0; e < E_EXP; ++e) {
            float factor = fmaxf(fabsf(sco[e]), max1);
            bool masked = (max1 - sco[e]) / factor > JITTER2;
            if (!masked) sum1 += expf(sco[e] - max1);
        }
        float mult1 = 1.0f / sum1;

        float max2 = -INFINITY; int ind2 = 0;
#pragma unroll
        for (int e = 0; e < E_EXP; ++e)
            if (e != ind1 && sco[e] > max2) { max2 = sco[e]; ind2 = e; }
        float sum2 = 0.0f;
#pragma unroll
        for (int e = 0; e < E_EXP; ++e) {
            if (e == ind1) continue;
            float factor = fmaxf(fabsf(sco[e]), max2);
            bool masked = (max2 - sco[e]) / factor > JITTER2;
            if (!masked) sum2 += expf(sco[e] - max2);
        }
        float mult2 = 1.0f / sum2;

        int p1 = atomicAdd(&g_cnt[ind1], 1);
        g_tok [ind1 * T_TOK + p1] = t;
        g_mult[ind1 * T_TOK + p1] = mult1;
        int p2 = atomicAdd(&g_cnt[ind2], 1);
        g_tok [ind2 * T_TOK + p2] = t;
        g_mult[ind2 * T_TOK + p2] = mult2;
    }
}

// ---------------------------------------------------------------------------
// Mainloop pieces.
// A fp16 tile: row r (128), 4 chunks of 16B; chunk c at r*64 + ((c^((r>>1)&3))<<4).
// B fp32 staging: row r (256), 8 chunks; chunk c at r*128 + ((c^(r&7))<<4).
// B fp16 tile: row r (256), 4 chunks; same swizzle as A.
// Requires in scope: smem_u32, smf, tid, pA, dA, pB[4], dB[4], dH[4].
// ---------------------------------------------------------------------------
#define ISSUE_T(j)                                                              \
    do {                                                                        \
        int _s = (j) % NSTG; int _ko = (j) * BKF;                               \
        uint32_t _ab = smem_u32 + _s * AH_STG;                                  \
        uint32_t _bb = smem_u32 + BF_OFF + _s * BF_STG;                         \
        cp16(_ab + dA, pA + _ko);                                               \
        _Pragma("unroll") for (int q = 0; q < 4; ++q) cp16(_bb + dB[q], pB[q] + _ko); \
        CP_COMMIT();                                                            \
    } while (0)

// Convert this thread's 4 fp32 B-chunks of tile j to fp16 tile j.
#define CVT_B(j)                                                                \
    do {                                                                        \
        int _s = (j) % NSTG;                                                    \
        char* _bf = smf + BF_OFF + _s * BF_STG;                                 \
        char* _bh = smf + BH_OFF + _s * BH_STG;                                 \
        _Pragma("unroll") for (int q = 0; q < 4; ++q) {                         \
            float4 _v = *(const float4*)(_bf + dB[q]);                          \
            uint2 _h;                                                           \
            _h.x = pack_f16x2(_v.x, _v.y);                                      \
            _h.y = pack_f16x2(_v.z, _v.w);                                      \
            *(uint2*)(_bh + dH[q]) = _h;                                        \
        }                                                                       \
    } while (0)

// Fragment compute for one k32 stage (two k16 steps).
#define COMPUTE_STAGE(stg)                                                      \
    do {                                                                        \
        uint32_t aS = smem_u32 + (stg) * AH_STG;                                \
        uint32_t gS = smem_u32 + BH_OFF + (stg) * BH_STG;                       \
        uint32_t uS = gS + 128 * 64;                                            \
        _Pragma("unroll")                                                       \
        for (int s = 0; s < 2; ++s) {                                           \
            uint32_t af[4][4], bgf[4], buf[4];                                  \
            _Pragma("unroll")                                                   \
            for (int mt = 0; mt < 4; ++mt)                                      \
                ldsm4(af[mt], aS + rowOffA[mt] +                                \
                      ((uint32_t)((2 * s + lhi) ^ swA[mt]) << 4));              \
            {                                                                   \
                uint32_t ch = (uint32_t)((2 * s + q1) ^ swB) << 4;              \
                ldsm4(bgf, gS + rowOffB + ch);                                  \
                ldsm4(buf, uS + rowOffB + ch);                                  \
            }                                                                   \
            _Pragma("unroll")                                                   \
            for (int mt = 0; mt < 4; ++mt) {                                    \
                mma_f16(accG[mt][0], af[mt], &bgf[0]);                          \
                mma_f16(accG[mt][1], af[mt], &bgf[2]);                          \
                mma_f16(accU[mt][0], af[mt], &buf[0]);                          \
                mma_f16(accU[mt][1], af[mt], &buf[2]);                          \
            }                                                                   \
        }                                                                       \
    } while (0)

// Pipelined mainloop, ONE barrier per iteration.
// iter t: compute stage t%3 (fp16 tile written by CVT(t) last iter, published
// by top barrier), CVT(t+1) (chunks this thread cp.async'd; CP_WAIT(1) makes
// group t+1 visible), ISSUE(t+2) overwrites stage (t-1)%3 freed by
// compute(t-1) which the top barrier ordered.
#define GEMM_MAINLOOP(NT)                                                       \
    ISSUE_T(0); ISSUE_T(1);                                                     \
    CP_WAIT(1);                                                                 \
    CVT_B(0);                                                                   \
    for (int t = 0; t < (NT); ++t) {                                            \
        __syncthreads();                                                        \
        if (t + 2 < (NT))      { ISSUE_T(t + 2); CP_WAIT(1); CVT_B(t + 1); }    \
        else if (t + 1 < (NT)) { CP_WAIT(0); CVT_B(t + 1); }                    \
        COMPUTE_STAGE(t % NSTG);                                                \
    }

// Per-warp/lane fragment setup. 16 warps: 2(m) x 8(n).
#define FRAG_SETUP()                                                            \
    int warp = tid >> 5, lane = tid & 31;                                       \
    int wm = (warp & 1) * 64, wn = (warp >> 1) * 16;                            \
    int tg = lane >> 2, tt = lane & 3;                                          \
    int l16 = lane & 15, lhi = lane >> 4, q1 = (lane >> 3) & 1;                 \
    uint32_t rowOffA[4], swA[4];                                                \
    _Pragma("unroll")                                                           \
    for (int mt = 0; mt < 4; ++mt) {                                            \
        int r = wm + mt * 16 + l16;                                             \
        rowOffA[mt] = (uint32_t)r * 64; swA[mt] = (uint32_t)((r >> 1) & 3);     \
    }                                                                           \
    uint32_t rowOffB, swB;                                                      \
    {                                                                           \
        int r = wn + ((lane >> 4) << 3) + (lane & 7);                           \
        rowOffB = (uint32_t)r * 64; swB = (uint32_t)((r >> 1) & 3);             \
    }                                                                           \
    float accG[4][2][4], accU[4][2][4];                                         \
    _Pragma("unroll")                                                           \
    for (int i = 0; i < 4; ++i)                                                 \
        _Pragma("unroll")                                                       \
        for (int j = 0; j < 2; ++j)                                             \
            _Pragma("unroll")                                                   \
            for (int r = 0; r < 4; ++r) { accG[i][j][r] = 0.f; accU[i][j][r] = 0.f; }

// ---------------------------------------------------------------------------
// GEMM 1 + fused SiLU: act[e,m,n] = f16(silu(x@wg^T) * (x@wu^T))
// CTA: 128 tokens x (128 gate cols n0.. + 128 up cols I+n0..). K = H = 2048.
// ---------------------------------------------------------------------------
__global__ __launch_bounds__(512, 1)
void k_ffn1(const float* __restrict__ ws) {
    int e  = blockIdx.z;
    int Me = g_cnt[e];
    int m0 = blockIdx.x * 128;
    if (m0 >= Me) return;
    int n0 = blockIdx.y * 128;

    extern __shared__ float sm_raw[];
    uint32_t raw_u32  = (uint32_t)__cvta_generic_to_shared(sm_raw);
    uint32_t smem_u32 = (raw_u32 + 1023) & ~1023u;
    char* smf = (char*)sm_raw + (smem_u32 - raw_u32);
    __shared__ int stok[128];

    int tid = threadIdx.x;
    if (tid < 128) {
        int m = m0 + tid;
        stok[tid] = (m < Me) ? g_tok[e * T_TOK + m] : g_tok[e * T_TOK];
    }
    __syncthreads();

    // A: 1 fp16 chunk (16B = 8 halves) per thread; rows have 4 chunks.
    int arow = tid >> 2, ac = tid & 3;
    const __half* pA = g_xh + (size_t)stok[arow] * H_DIM + ac * 8;
    uint32_t dA = arow * 64 + ((ac ^ ((arow >> 1) & 3)) << 4);

    // B fp32: 4 chunks/thread into staging; fp16 destinations precomputed.
    const float* pB[4]; uint32_t dB[4], dH[4];
    const float* wbase = ws + (size_t)e * TWO_I * H_DIM;
#pragma unroll
    for (int q = 0; q < 4; ++q) {
        int b = q * 512 + tid, r = b >> 3, c = b & 7;
        int rowg = (r < 128) ? (n0 + r) : (I_DIM + n0 + (r - 128));
        pB[q] = wbase + (size_t)rowg * H_DIM + c * 4;
        dB[q] = r * 128 + ((c ^ (r & 7)) << 4);
        dH[q] = r * 64 + (((c >> 1) ^ ((r >> 1) & 3)) << 4) + (c & 1) * 8;
    }

    FRAG_SETUP();
    GEMM_MAINLOOP(H_DIM / BKF);

    // epilogue: act = f16(silu(g) * u), packed pair stores
    __half* actb = g_acth + (size_t)e * T_TOK * I_DIM + n0;
#pragma unroll
    for (int mt = 0; mt < 4; ++mt)
#pragma unroll
        for (int rp = 0; rp < 2; ++rp) {
            int m = m0 + wm + mt * 16 + tg + rp * 8;
            if (m < Me) {
                __half* arw = actb + (size_t)m * I_DIM;
#pragma unroll
                for (int nt = 0; nt < 2; ++nt) {
                    int col = wn + nt * 8 + tt * 2;
                    float g0 = accG[mt][nt][rp * 2], g1 = accG[mt][nt][rp * 2 + 1];
                    float u0 = accU[mt][nt][rp * 2], u1 = accU[mt][nt][rp * 2 + 1];
                    float v0 = g0 / (1.0f + expf(-g0)) * u0;
                    float v1 = g1 / (1.0f + expf(-g1)) * u1;
                    *(uint32_t*)(arw + col) = pack_f16x2(v0, v1);
                }
            }
        }
}

// ---------------------------------------------------------------------------
// GEMM 2 + scatter: out[tok,n] += mult * (act @ w2s^T)
// CTA: 128 rows x 256 out cols, K-split x2 (blockIdx.y bit0).
// ---------------------------------------------------------------------------
__global__ __launch_bounds__(512, 1)
void k_ffn2(const float* __restrict__ w2s, float* __restrict__ out) {
    int e  = blockIdx.z;
    int Me = g_cnt[e];
    int m0 = blockIdx.x * 128;
    if (m0 >= Me) return;
    int n0  = (blockIdx.y >> 1) * 256;
    int kb0 = (blockIdx.y & 1) * (I_DIM / 2);

    extern __shared__ float sm_raw[];
    uint32_t raw_u32  = (uint32_t)__cvta_generic_to_shared(sm_raw);
    uint32_t smem_u32 = (raw_u32 + 1023) & ~1023u;
    char* smf = (char*)sm_raw + (smem_u32 - raw_u32);

    int tid = threadIdx.x;

    int arow = tid >> 2, ac = tid & 3;
    const __half* pA = g_acth + ((size_t)e * T_TOK + m0 + arow) * I_DIM + kb0 + ac * 8;
    uint32_t dA = arow * 64 + ((ac ^ ((arow >> 1) & 3)) << 4);

    const float* pB[4]; uint32_t dB[4], dH[4];
    const float* wbase = w2s + (size_t)e * H_DIM * I_DIM + kb0;
#pragma unroll
    for (int q = 0; q < 4; ++q) {
        int b = q * 512 + tid, r = b >> 3, c = b & 7;
        pB[q] = wbase + (size_t)(n0 + r) * I_DIM + c * 4;
        dB[q] = r * 128 + ((c ^ (r & 7)) << 4);
        dH[q] = r * 64 + (((c >> 1) ^ ((r >> 1) & 3)) << 4) + (c & 1) * 8;
    }

    FRAG_SETUP();
    GEMM_MAINLOOP((I_DIM / 2) / BKF);

    // scatter epilogue: out[tok, n] += mult * v  (commutative adds)
#pragma unroll
    for (int mt = 0; mt < 4; ++mt)
#pragma unroll
        for (int rp = 0; rp < 2; ++rp) {
            int ml = m0 + wm + mt * 16 + tg + rp * 8;
            if (ml < Me) {
                int   tok = g_tok [e * T_TOK + ml];
                float mu  = g_mult[e * T_TOK + ml];
                float* dst = out + (size_t)tok * H_DIM + n0;
#pragma unroll
                for (int nt = 0; nt < 2; ++nt) {
                    int col = wn + nt * 8 + tt * 2;
                    atomicAdd(dst + col,           mu * accG[mt][nt][rp * 2]);
                    atomicAdd(dst + col + 1,       mu * accG[mt][nt][rp * 2 + 1]);
                    atomicAdd(dst + 128 + col,     mu * accU[mt][nt][rp * 2]);
                    atomicAdd(dst + 128 + col + 1, mu * accU[mt][nt][rp * 2 + 1]);
                }
            }
        }
}

// ---------------------------------------------------------------------------
// Launch
// ---------------------------------------------------------------------------
extern "C" void kernel_launch(void* const* d_in, const int* in_sizes, int n_in,
                              void* d_out, int out_size) {
    (void)in_sizes; (void)n_in; (void)out_size;
    const float* x   = (const float*)d_in[0];   // [T, H]
    const float* gw  = (const float*)d_in[1];   // [E, H]
    const float* ws  = (const float*)d_in[2];   // [E, 2I, H]
    const float* w2s = (const float*)d_in[3];   // [E, H, I]
    float* out = (float*)d_out;                 // [T, H]

    cudaFuncSetAttribute(k_ffn1, cudaFuncAttributeMaxDynamicSharedMemorySize, SMEMB);
    cudaFuncSetAttribute(k_ffn2, cudaFuncAttributeMaxDynamicSharedMemorySize, SMEMB);

    k_init<<<(T_TOK * H_DIM + 255) / 256, 256>>>(out);
    k_cvt_x<<<(T_TOK * H_DIM / 4 + 255) / 256, 256>>>(x);
    k_router<<<T_TOK, 256>>>(x, gw);
    k_ffn1<<<dim3(T_TOK / 128, I_DIM / 128, E_EXP), 512, SMEMB>>>(ws);
    k_ffn2<<<dim3(T_TOK / 128, (H_DIM / 256) * 2, E_EXP), 512, SMEMB>>>(w2s, out);
}

// round 17
// speedup vs baseline: 6.9229x; 1.1002x over previous
#include <cuda_runtime.h>
#include <cuda_fp16.h>
#include <math.h>
#include <stdint.h>

// Problem constants: T=1024 tokens, H=2048 hidden, I=4096 intermediate, E=8.
#define T_TOK 1024
#define H_DIM 2048
#define I_DIM 4096
#define E_EXP 8
#define TWO_I (2 * I_DIM)
#define JITTER2 0.02f   // 2 * JITTER_EPS

// GEMM tiling: CTA tile M=128 x N=256 (two 128-halves), BK=32 (k16 x2 per tile).
// 512 threads / 16 warps as 2(m) x 8(n); warp tile 64(m) x 16(n) per G/U half.
// A fp16 smem: 3 stages x 8KB. B fp16 smem: 2 stages x 16KB. No fp32 staging:
// weights go LDG.128 -> regs -> cvt -> STS.64 fp16.
#define BKF     32
#define AH_STG  8192                         // 128 rows * 64 B
#define BH_STG  16384                        // 256 rows * 64 B
#define BH_OFF  (3 * AH_STG)                 // 24576
#define SMEMB   (BH_OFF + 2 * BH_STG + 1024) // 58368

// ---------------------------------------------------------------------------
// Device-global scratch (allocation-free rule)
// ---------------------------------------------------------------------------
__device__ int   g_cnt[E_EXP];
__device__ int   g_tok [E_EXP * T_TOK];
__device__ float g_mult[E_EXP * T_TOK];
__device__ __align__(128) __half g_xh [(size_t)T_TOK * H_DIM];           // fp16 x
__device__ __align__(128) __half g_acth[(size_t)E_EXP * T_TOK * I_DIM];  // fp16 act

// ---------------------------------------------------------------------------
// Helpers
// ---------------------------------------------------------------------------
__device__ __forceinline__ uint32_t pack_f16x2(float lo, float hi) {
    uint32_t r;  // PTX: cvt d, a, b -> hi=cvt(a), lo=cvt(b)
    asm("cvt.rn.f16x2.f32 %0, %1, %2;" : "=r"(r) : "f"(hi), "f"(lo));
    return r;
}

__device__ __forceinline__ void mma_f16(float* c, const uint32_t* a, const uint32_t* b) {
    asm volatile(
        "mma.sync.aligned.m16n8k16.row.col.f32.f16.f16.f32 "
        "{%0,%1,%2,%3}, {%4,%5,%6,%7}, {%8,%9}, {%0,%1,%2,%3};"
        : "+f"(c[0]), "+f"(c[1]), "+f"(c[2]), "+f"(c[3])
        : "r"(a[0]), "r"(a[1]), "r"(a[2]), "r"(a[3]), "r"(b[0]), "r"(b[1]));
}

__device__ __forceinline__ void ldsm4(uint32_t* r, uint32_t addr) {
    asm volatile(
        "ldmatrix.sync.aligned.m8n8.x4.shared.b16 {%0,%1,%2,%3}, [%4];"
        : "=r"(r[0]), "=r"(r[1]), "=r"(r[2]), "=r"(r[3]) : "r"(addr));
}

__device__ __forceinline__ void cp16(uint32_t dst, const void* src) {
    asm volatile("cp.async.cg.shared.global [%0], [%1], 16;" :: "r"(dst), "l"(src) : "memory");
}
#define CP_COMMIT() asm volatile("cp.async.commit_group;" ::: "memory")
#define CP_WAIT(n)  asm volatile("cp.async.wait_group %0;" :: "n"(n) : "memory")

// ---------------------------------------------------------------------------
// Kernel 0: zero output + expert counters
// ---------------------------------------------------------------------------
__global__ void k_init(float* __restrict__ out) {
    int i = blockIdx.x * blockDim.x + threadIdx.x;
    if (i < E_EXP) g_cnt[i] = 0;
    if (i < T_TOK * H_DIM) out[i] = 0.0f;
}

// Convert x to fp16 once (A-side of ffn1)
__global__ void k_cvt_x(const float* __restrict__ x) {
    int i = blockIdx.x * blockDim.x + threadIdx.x;   // float4 index
    float4 v = ((const float4*)x)[i];
    uint2 h;
    h.x = pack_f16x2(v.x, v.y);
    h.y = pack_f16x2(v.z, v.w);
    ((uint2*)g_xh)[i] = h;
}

// ---------------------------------------------------------------------------
// Kernel 1: router + sparsemixer + per-expert token lists (unchanged, passing)
// ---------------------------------------------------------------------------
__global__ void k_router(const float* __restrict__ x, const float* __restrict__ gw) {
    int t    = blockIdx.x;
    int warp = threadIdx.x >> 5;
    int lane = threadIdx.x & 31;

    const float4* xr = (const float4*)(x + (size_t)t * H_DIM);
    const float4* gr = (const float4*)(gw + (size_t)warp * H_DIM);

    float s = 0.0f;
    for (int i = lane; i < H_DIM / 4; i += 32) {
        float4 a = xr[i];
        float4 b = gr[i];
        s += a.x * b.x + a.y * b.y + a.z * b.z + a.w * b.w;
    }
#pragma unroll
    for (int o = 16; o > 0; o >>= 1) s += __shfl_xor_sync(0xFFFFFFFFu, s, o);

    __shared__ float sc[E_EXP];
    if (lane == 0) sc[warp] = s;
    __syncthreads();

    if (threadIdx.x == 0) {
        float sco[E_EXP];
#pragma unroll
        for (int e = 0; e < E_EXP; ++e) sco[e] = sc[e];

        float max1 = sco[0]; int ind1 = 0;
#pragma unroll
        for (int e = 1; e < E_EXP; ++e)
            if (sco[e] > max1) { max1 = sco[e]; ind1 = e; }
        float sum1 = 0.0f;
#pragma unroll
        for (int e = 0; e < E_EXP; ++e) {
            float factor = fmaxf(fabsf(sco[e]), max1);
            bool masked = (max1 - sco[e]) / factor > JITTER2;
            if (!masked) sum1 += expf(sco[e] - max1);
        }
        float mult1 = 1.0f / sum1;

        float max2 = -INFINITY; int ind2 = 0;
#pragma unroll
        for (int e = 0; e < E_EXP; ++e)
            if (e != ind1 && sco[e] > max2) { max2 = sco[e]; ind2 = e; }
        float sum2 = 0.0f;
#pragma unroll
        for (int e = 0; e < E_EXP; ++e) {
            if (e == ind1) continue;
            float factor = fmaxf(fabsf(sco[e]), max2);
            bool masked = (max2 - sco[e]) / factor > JITTER2;
            if (!masked) sum2 += expf(sco[e] - max2);
        }
        float mult2 = 1.0f / sum2;

        int p1 = atomicAdd(&g_cnt[ind1], 1);
        g_tok [ind1 * T_TOK + p1] = t;
        g_mult[ind1 * T_TOK + p1] = mult1;
        int p2 = atomicAdd(&g_cnt[ind2], 1);
        g_tok [ind2 * T_TOK + p2] = t;
        g_mult[ind2 * T_TOK + p2] = mult2;
    }
}

// ---------------------------------------------------------------------------
// Mainloop pieces.
// A fp16 tile (per stage): row r (128), 4 chunks of 16B;
//   chunk c at r*64 + ((c ^ ((r>>1)&3))<<4).
// B fp16 tile: 256 rows x 64B, same swizzle.
// Per thread: rr = tid>>3 (row within 64-row group), cc = tid&7 (fp32 chunk).
// B fp32 rows covered: q*64 + rr, q = 0..3 (q<2 -> gate base bG, q>=2 -> bU).
// Requires in scope: smem_u32, smf, tid, pA, dA, bG, bU, dH0, w4[4].
// ---------------------------------------------------------------------------
#define ISSUE_A(j)                                                              \
    do {                                                                        \
        int _s = (j) % 3;                                                       \
        cp16(smem_u32 + _s * AH_STG + dA, pA + (j) * BKF);                      \
        CP_COMMIT();                                                            \
    } while (0)

#define LDG_B(j, STR)                                                           \
    do {                                                                        \
        int _ko = (j) * BKF;                                                    \
        w4[0] = __ldg((const float4*)(bG + _ko));                               \
        w4[1] = __ldg((const float4*)(bG + (size_t)64 * (STR) + _ko));          \
        w4[2] = __ldg((const float4*)(bU + _ko));                               \
        w4[3] = __ldg((const float4*)(bU + (size_t)64 * (STR) + _ko));          \
    } while (0)

#define STS_B(j)                                                                \
    do {                                                                        \
        int _s = (j) & 1;                                                       \
        char* _bh = smf + BH_OFF + _s * BH_STG;                                 \
        _Pragma("unroll") for (int q = 0; q < 4; ++q) {                         \
            float4 _v = w4[q];                                                  \
            uint2 _h;                                                           \
            _h.x = pack_f16x2(_v.x, _v.y);                                      \
            _h.y = pack_f16x2(_v.z, _v.w);                                      \
            *(uint2*)(_bh + dH0 + q * 4096) = _h;                               \
        }                                                                       \
    } while (0)

// Fragment compute for one k32 tile: A stage sa (of 3), B stage sb (of 2).
#define COMPUTE_STAGE(sa, sb)                                                   \
    do {                                                                        \
        uint32_t aS = smem_u32 + (sa) * AH_STG;                                 \
        uint32_t gS = smem_u32 + BH_OFF + (sb) * BH_STG;                        \
        uint32_t uS = gS + 128 * 64;                                            \
        _Pragma("unroll")                                                       \
        for (int s = 0; s < 2; ++s) {                                           \
            uint32_t af[4][4], bgf[4], buf[4];                                  \
            _Pragma("unroll")                                                   \
            for (int mt = 0; mt < 4; ++mt)                                      \
                ldsm4(af[mt], aS + rowOffA[mt] +                                \
                      ((uint32_t)((2 * s + lhi) ^ swA[mt]) << 4));              \
            {                                                                   \
                uint32_t ch = (uint32_t)((2 * s + q1) ^ swB) << 4;              \
                ldsm4(bgf, gS + rowOffB + ch);                                  \
                ldsm4(buf, uS + rowOffB + ch);                                  \
            }                                                                   \
            _Pragma("unroll")                                                   \
            for (int mt = 0; mt < 4; ++mt) {                                    \
                mma_f16(accG[mt][0], af[mt], &bgf[0]);                          \
                mma_f16(accG[mt][1], af[mt], &bgf[2]);                          \
                mma_f16(accU[mt][0], af[mt], &buf[0]);                          \
                mma_f16(accU[mt][1], af[mt], &buf[2]);                          \
            }                                                                   \
        }                                                                       \
    } while (0)

// Pipelined mainloop, ONE barrier per iteration.
// iter t: compute A stage t%3 / B stage t&1. STS_B(t+1) writes B stage (t+1)&1
// (last read by compute(t-1), ordered by this iter's barrier). ISSUE_A(t+2)
// writes A stage (t+2)%3 = (t-1)%3 (freed by compute(t-1)). LDG_B(t+2)
// refills the register buffer after STS_B(t+1) consumed it; its data is used
// one full compute stage later (covers L2 latency). CP_WAIT(1) at iter t
// leaves group A(t+1) in flight, guaranteeing A(t) landed before the barrier.
#define GEMM_MAINLOOP(NT, STR)                                                  \
    LDG_B(0, STR); ISSUE_A(0);                                                  \
    STS_B(0);                                                                   \
    LDG_B(1, STR); ISSUE_A(1);                                                  \
    for (int t = 0; t < (NT); ++t) {                                            \
        if (t + 1 < (NT)) { CP_WAIT(1); } else { CP_WAIT(0); }                  \
        __syncthreads();                                                        \
        if (t + 1 < (NT)) {                                                     \
            STS_B(t + 1);                                                       \
            if (t + 2 < (NT)) { LDG_B(t + 2, STR); ISSUE_A(t + 2); }            \
        }                                                                       \
        COMPUTE_STAGE(t % 3, t & 1);                                            \
    }

// Per-warp/lane fragment setup. 16 warps: 2(m) x 8(n).
#define FRAG_SETUP()                                                            \
    int warp = tid >> 5, lane = tid & 31;                                       \
    int wm = (warp & 1) * 64, wn = (warp >> 1) * 16;                            \
    int tg = lane >> 2, tt = lane & 3;                                          \
    int l16 = lane & 15, lhi = lane >> 4, q1 = (lane >> 3) & 1;                 \
    uint32_t rowOffA[4], swA[4];                                                \
    _Pragma("unroll")                                                           \
    for (int mt = 0; mt < 4; ++mt) {                                            \
        int r = wm + mt * 16 + l16;                                             \
        rowOffA[mt] = (uint32_t)r * 64; swA[mt] = (uint32_t)((r >> 1) & 3);     \
    }                                                                           \
    uint32_t rowOffB, swB;                                                      \
    {                                                                           \
        int r = wn + ((lane >> 4) << 3) + (lane & 7);                           \
        rowOffB = (uint32_t)r * 64; swB = (uint32_t)((r >> 1) & 3);             \
    }                                                                           \
    float accG[4][2][4], accU[4][2][4];                                         \
    _Pragma("unroll")                                                           \
    for (int i = 0; i < 4; ++i)                                                 \
        _Pragma("unroll")                                                       \
        for (int j = 0; j < 2; ++j)                                             \
            _Pragma("unroll")                                                   \
            for (int r = 0; r < 4; ++r) { accG[i][j][r] = 0.f; accU[i][j][r] = 0.f; }

// B-side per-thread indices shared by both kernels.
#define B_IDX_SETUP()                                                           \
    int rr = tid >> 3, cc = tid & 7;                                            \
    uint32_t dH0 = (uint32_t)rr * 64 +                                          \
                   ((uint32_t)((cc >> 1) ^ ((rr >> 1) & 3)) << 4) +             \
                   (uint32_t)(cc & 1) * 8;                                      \
    float4 w4[4];

// ---------------------------------------------------------------------------
// GEMM 1 + fused SiLU: act[e,m,n] = f16(silu(x@wg^T) * (x@wu^T))
// CTA: 128 tokens x (128 gate cols n0.. + 128 up cols I+n0..). K = H = 2048.
// ---------------------------------------------------------------------------
__global__ __launch_bounds__(512, 1)
void k_ffn1(const float* __restrict__ ws) {
    int e  = blockIdx.z;
    int Me = g_cnt[e];
    int m0 = blockIdx.x * 128;
    if (m0 >= Me) return;
    int n0 = blockIdx.y * 128;

    extern __shared__ float sm_raw[];
    uint32_t raw_u32  = (uint32_t)__cvta_generic_to_shared(sm_raw);
    uint32_t smem_u32 = (raw_u32 + 1023) & ~1023u;
    char* smf = (char*)sm_raw + (smem_u32 - raw_u32);
    __shared__ int stok[128];

    int tid = threadIdx.x;
    if (tid < 128) {
        int m = m0 + tid;
        stok[tid] = (m < Me) ? g_tok[e * T_TOK + m] : g_tok[e * T_TOK];
    }
    __syncthreads();

    // A: 1 fp16 chunk (16B) per thread per tile; rows have 4 chunks.
    int arow = tid >> 2, ac = tid & 3;
    const __half* pA = g_xh + (size_t)stok[arow] * H_DIM + ac * 8;
    uint32_t dA = arow * 64 + ((ac ^ ((arow >> 1) & 3)) << 4);

    B_IDX_SETUP();
    const float* wbase = ws + (size_t)e * TWO_I * H_DIM;
    const float* bG = wbase + (size_t)(n0 + rr) * H_DIM + cc * 4;
    const float* bU = wbase + (size_t)(I_DIM + n0 + rr) * H_DIM + cc * 4;

    FRAG_SETUP();
    GEMM_MAINLOOP(H_DIM / BKF, H_DIM);

    // epilogue: act = f16(silu(g) * u), packed pair stores
    __half* actb = g_acth + (size_t)e * T_TOK * I_DIM + n0;
#pragma unroll
    for (int mt = 0; mt < 4; ++mt)
#pragma unroll
        for (int rp = 0; rp < 2; ++rp) {
            int m = m0 + wm + mt * 16 + tg + rp * 8;
            if (m < Me) {
                __half* arw = actb + (size_t)m * I_DIM;
#pragma unroll
                for (int nt = 0; nt < 2; ++nt) {
                    int col = wn + nt * 8 + tt * 2;
                    float g0 = accG[mt][nt][rp * 2], g1 = accG[mt][nt][rp * 2 + 1];
                    float u0 = accU[mt][nt][rp * 2], u1 = accU[mt][nt][rp * 2 + 1];
                    float v0 = g0 / (1.0f + expf(-g0)) * u0;
                    float v1 = g1 / (1.0f + expf(-g1)) * u1;
                    *(uint32_t*)(arw + col) = pack_f16x2(v0, v1);
                }
            }
        }
}

// ---------------------------------------------------------------------------
// GEMM 2 + scatter: out[tok,n] += mult * (act @ w2s^T)
// CTA: 128 rows x 256 out cols, K-split x2 (blockIdx.y bit0).
// ---------------------------------------------------------------------------
__global__ __launch_bounds__(512, 1)
void k_ffn2(const float* __restrict__ w2s, float* __restrict__ out) {
    int e  = blockIdx.z;
    int Me = g_cnt[e];
    int m0 = blockIdx.x * 128;
    if (m0 >= Me) return;
    int n0  = (blockIdx.y >> 1) * 256;
    int kb0 = (blockIdx.y & 1) * (I_DIM / 2);

    extern __shared__ float sm_raw[];
    uint32_t raw_u32  = (uint32_t)__cvta_generic_to_shared(sm_raw);
    uint32_t smem_u32 = (raw_u32 + 1023) & ~1023u;
    char* smf = (char*)sm_raw + (smem_u32 - raw_u32);

    int tid = threadIdx.x;

    int arow = tid >> 2, ac = tid & 3;
    const __half* pA = g_acth + ((size_t)e * T_TOK + m0 + arow) * I_DIM + kb0 + ac * 8;
    uint32_t dA = arow * 64 + ((ac ^ ((arow >> 1) & 3)) << 4);

    B_IDX_SETUP();
    const float* wbase = w2s + (size_t)e * H_DIM * I_DIM + kb0;
    const float* bG = wbase + (size_t)(n0 + rr) * I_DIM + cc * 4;
    const float* bU = bG + (size_t)128 * I_DIM;

    FRAG_SETUP();
    GEMM_MAINLOOP((I_DIM / 2) / BKF, I_DIM);

    // scatter epilogue: out[tok, n] += mult * v  (commutative adds)
#pragma unroll
    for (int mt = 0; mt < 4; ++mt)
#pragma unroll
        for (int rp = 0; rp < 2; ++rp) {
            int ml = m0 + wm + mt * 16 + tg + rp * 8;
            if (ml < Me) {
                int   tok = g_tok [e * T_TOK + ml];
                float mu  = g_mult[e * T_TOK + ml];
                float* dst = out + (size_t)tok * H_DIM + n0;
#pragma unroll
                for (int nt = 0; nt < 2; ++nt) {
                    int col = wn + nt * 8 + tt * 2;
                    atomicAdd(dst + col,           mu * accG[mt][nt][rp * 2]);
                    atomicAdd(dst + col + 1,       mu * accG[mt][nt][rp * 2 + 1]);
                    atomicAdd(dst + 128 + col,     mu * accU[mt][nt][rp * 2]);
                    atomicAdd(dst + 128 + col + 1, mu * accU[mt][nt][rp * 2 + 1]);
                }
            }
        }
}

// ---------------------------------------------------------------------------
// Launch
// ---------------------------------------------------------------------------
extern "C" void kernel_launch(void* const* d_in, const int* in_sizes, int n_in,
                              void* d_out, int out_size) {
    (void)in_sizes; (void)n_in; (void)out_size;
    const float* x   = (const float*)d_in[0];   // [T, H]
    const float* gw  = (const float*)d_in[1];   // [E, H]
    const float* ws  = (const float*)d_in[2];   // [E, 2I, H]
    const float* w2s = (const float*)d_in[3];   // [E, H, I]
    float* out = (float*)d_out;                 // [T, H]

    cudaFuncSetAttribute(k_ffn1, cudaFuncAttributeMaxDynamicSharedMemorySize, SMEMB);
    cudaFuncSetAttribute(k_ffn2, cudaFuncAttributeMaxDynamicSharedMemorySize, SMEMB);

    k_init<<<(T_TOK * H_DIM + 255) / 256, 256>>>(out);
    k_cvt_x<<<(T_TOK * H_DIM / 4 + 255) / 256, 256>>>(x);
    k_router<<<T_TOK, 256>>>(x, gw);
    k_ffn1<<<dim3(T_TOK / 128, I_DIM / 128, E_EXP), 512, SMEMB>>>(ws);
    k_ffn2<<<dim3(T_TOK / 128, (H_DIM / 256) * 2, E_EXP), 512, SMEMB>>>(w2s, out);
}